// round 1
// baseline (speedup 1.0000x reference)
#include <cuda_runtime.h>
#include <cuda_bf16.h>
#include <mma.h>
#include <math.h>

using namespace nvcuda;

#define BATCH 2
#define SEQ   2048
#define DIMSZ 4096
#define NH    32
#define NKV   8
#define HD    128
#define MTOK  (BATCH * SEQ)   // 4096 tokens

// ---------------- scratch (static device memory; no allocs allowed) ----------
__device__ float g_q[(size_t)MTOK * NH * HD];     // 67 MB
__device__ float g_k[(size_t)MTOK * NKV * HD];    // 16.8 MB
__device__ float g_v[(size_t)MTOK * NKV * HD];    // 16.8 MB
__device__ float g_attn[(size_t)MTOK * NH * HD];  // 67 MB

// ---------------- tf32 WMMA GEMM: C[M,N] = A[M,K] @ B[K,N], all row-major ----
// Block tile 128x128, K-step 32. 8 warps in 4x2 grid, each warp 32x64 (2x4 wmma tiles).
#define GA_LD 40    // 128x32 A tile, padded row stride (floats); 160B, mult of 16B
#define GB_LD 136   // 32x128 B tile, padded row stride; 544B, mult of 16B

__global__ __launch_bounds__(256, 1) void gemm_tf32(
    const float* __restrict__ A, const float* __restrict__ B,
    float* __restrict__ C, int Ndim, int Kdim)
{
    __shared__ float As[128 * GA_LD];
    __shared__ float Bs[32 * GB_LD];

    const int tid = threadIdx.x;
    const int bm = blockIdx.y * 128;
    const int bn = blockIdx.x * 128;
    const int warp = tid >> 5;
    const int wr = warp >> 1;   // 0..3
    const int wc = warp & 1;    // 0..1

    wmma::fragment<wmma::accumulator, 16, 16, 8, float> acc[2][4];
#pragma unroll
    for (int i = 0; i < 2; i++)
#pragma unroll
        for (int j = 0; j < 4; j++)
            wmma::fill_fragment(acc[i][j], 0.0f);

    for (int k0 = 0; k0 < Kdim; k0 += 32) {
        // Load A tile 128x32 (1024 float4s, 4 per thread)
#pragma unroll
        for (int i = 0; i < 4; i++) {
            int fid = tid + i * 256;
            int r = fid >> 3;
            int c4 = (fid & 7) << 2;
            float4 vv = *(const float4*)&A[(size_t)(bm + r) * Kdim + k0 + c4];
            *(float4*)&As[r * GA_LD + c4] = vv;
        }
        // Load B tile 32x128 (1024 float4s, 4 per thread)
#pragma unroll
        for (int i = 0; i < 4; i++) {
            int fid = tid + i * 256;
            int r = fid >> 5;
            int c4 = (fid & 31) << 2;
            float4 vv = *(const float4*)&B[(size_t)(k0 + r) * Ndim + bn + c4];
            *(float4*)&Bs[r * GB_LD + c4] = vv;
        }
        __syncthreads();

#pragma unroll
        for (int kk = 0; kk < 32; kk += 8) {
            wmma::fragment<wmma::matrix_a, 16, 16, 8, wmma::precision::tf32, wmma::row_major> af[2];
            wmma::fragment<wmma::matrix_b, 16, 16, 8, wmma::precision::tf32, wmma::row_major> bf[4];
#pragma unroll
            for (int i = 0; i < 2; i++) {
                wmma::load_matrix_sync(af[i], &As[(wr * 32 + i * 16) * GA_LD + kk], GA_LD);
                for (int t = 0; t < af[i].num_elements; t++)
                    af[i].x[t] = wmma::__float_to_tf32(af[i].x[t]);
            }
#pragma unroll
            for (int j = 0; j < 4; j++) {
                wmma::load_matrix_sync(bf[j], &Bs[kk * GB_LD + wc * 64 + j * 16], GB_LD);
                for (int t = 0; t < bf[j].num_elements; t++)
                    bf[j].x[t] = wmma::__float_to_tf32(bf[j].x[t]);
            }
#pragma unroll
            for (int i = 0; i < 2; i++)
#pragma unroll
                for (int j = 0; j < 4; j++)
                    wmma::mma_sync(acc[i][j], af[i], bf[j], acc[i][j]);
        }
        __syncthreads();
    }

#pragma unroll
    for (int i = 0; i < 2; i++)
#pragma unroll
        for (int j = 0; j < 4; j++)
            wmma::store_matrix_sync(
                &C[(size_t)(bm + wr * 32 + i * 16) * Ndim + bn + wc * 64 + j * 16],
                acc[i][j], Ndim, wmma::mem_row_major);
}

// ---------------- RoPE (interleaved pairs), fp64 range reduction -------------
__global__ void rope_kernel(float* __restrict__ t, int nheads, int total)
{
    int idx = blockIdx.x * blockDim.x + threadIdx.x;
    if (idx >= total) return;
    int p = idx & 63;            // pair index 0..63
    int rest = idx >> 6;
    int head = rest % nheads;
    int tok = rest / nheads;
    int pos = tok & (SEQ - 1);   // position within sequence

    // inv = theta^(-2p/128); angle computed like reference (fp32 pos*inv),
    // then reduced mod 2pi in fp64 so sin/cos stay accurate even under fast-math.
    double inv = exp(((double)(-2 * p) / 128.0) * log(500000.0));
    float angf = (float)pos * (float)inv;
    double ar = fmod((double)angf, 6.283185307179586476925287);
    float fa = (float)ar;
    float c = cosf(fa);
    float s = sinf(fa);

    float* base = t + ((size_t)tok * nheads + head) * HD + 2 * p;
    float a = base[0], b = base[1];
    base[0] = a * c - b * s;
    base[1] = a * s + b * c;
}

// ---------------- fp32 SIMT flash attention ----------------------------------
// grid (32 q-tiles, 64 batch*head), block 256.
// Q/K/V tiles 64x128 in smem (stride 132), S tile 64x64 (stride 65).
#define QK_LD 132
#define S_LD  65
#define ATTN_SMEM_FLOATS (3 * 64 * QK_LD + 64 * S_LD + 3 * 64)
#define ATTN_SMEM_BYTES  (ATTN_SMEM_FLOATS * 4)

__global__ __launch_bounds__(256, 1) void attn_kernel(
    const float* __restrict__ q, const float* __restrict__ k,
    const float* __restrict__ v, float* __restrict__ o)
{
    extern __shared__ float sm[];
    float* Qs = sm;                     // 64 x 132
    float* Ks = Qs + 64 * QK_LD;        // 64 x 132
    float* Vs = Ks + 64 * QK_LD;        // 64 x 132
    float* Ss = Vs + 64 * QK_LD;        // 64 x 65
    float* rowm = Ss + 64 * S_LD;       // 64 running max
    float* rowl = rowm + 64;            // 64 running sum
    float* salpha = rowl + 64;          // 64 rescale factors

    const int tid = threadIdx.x;
    const int tx = tid & 15;
    const int ty = tid >> 4;
    const int qtile = blockIdx.x;
    const int bh = blockIdx.y;
    const int b = bh / NH;
    const int h = bh % NH;
    const int kvh = h / (NH / NKV);
    const float scale = 0.08838834764831845f;  // 1/sqrt(128)

    // Load Q tile (pre-scaled)
#pragma unroll
    for (int i = 0; i < 8; i++) {
        int fid = tid + i * 256;        // 2048 float4s total
        int r = fid >> 5;
        int c4 = (fid & 31) << 2;
        int sq = qtile * 64 + r;
        float4 vq = *(const float4*)&q[(((size_t)(b * SEQ + sq)) * NH + h) * HD + c4];
        vq.x *= scale; vq.y *= scale; vq.z *= scale; vq.w *= scale;
        *(float4*)&Qs[r * QK_LD + c4] = vq;
    }
    if (tid < 64) { rowm[tid] = -INFINITY; rowl[tid] = 0.0f; }

    float Oacc[4][8];
#pragma unroll
    for (int i = 0; i < 4; i++)
#pragma unroll
        for (int cc = 0; cc < 8; cc++) Oacc[i][cc] = 0.0f;
    __syncthreads();

    for (int kt = 0; kt <= qtile; kt++) {
        // Load K and V tiles
#pragma unroll
        for (int i = 0; i < 8; i++) {
            int fid = tid + i * 256;
            int r = fid >> 5;
            int c4 = (fid & 31) << 2;
            int sk = kt * 64 + r;
            size_t gidx = (((size_t)(b * SEQ + sk)) * NKV + kvh) * HD + c4;
            *(float4*)&Ks[r * QK_LD + c4] = *(const float4*)&k[gidx];
            *(float4*)&Vs[r * QK_LD + c4] = *(const float4*)&v[gidx];
        }
        __syncthreads();

        // S = Q @ K^T  (64x64); thread (tx,ty) owns rows ty+16i, cols tx+16j
        float racc[4][4];
#pragma unroll
        for (int i = 0; i < 4; i++)
#pragma unroll
            for (int j = 0; j < 4; j++) racc[i][j] = 0.0f;

        for (int d4 = 0; d4 < 32; d4++) {
            float4 qv[4], kv[4];
#pragma unroll
            for (int i = 0; i < 4; i++)
                qv[i] = *(const float4*)&Qs[(ty + 16 * i) * QK_LD + d4 * 4];
#pragma unroll
            for (int j = 0; j < 4; j++)
                kv[j] = *(const float4*)&Ks[(tx + 16 * j) * QK_LD + d4 * 4];
#pragma unroll
            for (int i = 0; i < 4; i++)
#pragma unroll
                for (int j = 0; j < 4; j++) {
                    racc[i][j] += qv[i].x * kv[j].x;
                    racc[i][j] += qv[i].y * kv[j].y;
                    racc[i][j] += qv[i].z * kv[j].z;
                    racc[i][j] += qv[i].w * kv[j].w;
                }
        }

        const bool diag = (kt == qtile);
#pragma unroll
        for (int i = 0; i < 4; i++)
#pragma unroll
            for (int j = 0; j < 4; j++) {
                int r = ty + 16 * i, c = tx + 16 * j;
                float val = racc[i][j];
                if (diag && c > r) val = -1e9f;
                Ss[r * S_LD + c] = val;
            }
        __syncthreads();

        // Online softmax stats
        if (tid < 64) {
            float mold = rowm[tid];
            float mx = mold;
            const float* sr = &Ss[tid * S_LD];
#pragma unroll 8
            for (int c = 0; c < 64; c++) mx = fmaxf(mx, sr[c]);
            rowm[tid] = mx;
            salpha[tid] = __expf(mold - mx);  // 0 on first tile (mold=-inf)
        }
        __syncthreads();

        // Exponentiate in place
        for (int idx2 = tid; idx2 < 4096; idx2 += 256) {
            int r = idx2 >> 6, c = idx2 & 63;
            Ss[r * S_LD + c] = __expf(Ss[r * S_LD + c] - rowm[r]);
        }
        __syncthreads();

        // Row sums -> running l
        if (tid < 64) {
            float ssum = 0.0f;
            const float* sr = &Ss[tid * S_LD];
#pragma unroll 8
            for (int c = 0; c < 64; c++) ssum += sr[c];
            rowl[tid] = rowl[tid] * salpha[tid] + ssum;
        }

        // O = O*alpha + P @ V ; thread owns rows ty+16i, cols tx*8..tx*8+7
#pragma unroll
        for (int i = 0; i < 4; i++) {
            float a = salpha[ty + 16 * i];
#pragma unroll
            for (int cc = 0; cc < 8; cc++) Oacc[i][cc] *= a;
        }
        for (int c = 0; c < 64; c++) {
            float pv[4];
#pragma unroll
            for (int i = 0; i < 4; i++) pv[i] = Ss[(ty + 16 * i) * S_LD + c];
            float4 v0 = *(const float4*)&Vs[c * QK_LD + tx * 8];
            float4 v1 = *(const float4*)&Vs[c * QK_LD + tx * 8 + 4];
#pragma unroll
            for (int i = 0; i < 4; i++) {
                Oacc[i][0] += pv[i] * v0.x;
                Oacc[i][1] += pv[i] * v0.y;
                Oacc[i][2] += pv[i] * v0.z;
                Oacc[i][3] += pv[i] * v0.w;
                Oacc[i][4] += pv[i] * v1.x;
                Oacc[i][5] += pv[i] * v1.y;
                Oacc[i][6] += pv[i] * v1.z;
                Oacc[i][7] += pv[i] * v1.w;
            }
        }
        __syncthreads();
    }

    // Write normalized output
#pragma unroll
    for (int i = 0; i < 4; i++) {
        int r = ty + 16 * i;
        int sq = qtile * 64 + r;
        float invl = 1.0f / rowl[r];
        float4 o0, o1;
        o0.x = Oacc[i][0] * invl; o0.y = Oacc[i][1] * invl;
        o0.z = Oacc[i][2] * invl; o0.w = Oacc[i][3] * invl;
        o1.x = Oacc[i][4] * invl; o1.y = Oacc[i][5] * invl;
        o1.z = Oacc[i][6] * invl; o1.w = Oacc[i][7] * invl;
        float* op = &o[(((size_t)(b * SEQ + sq)) * NH + h) * HD + tx * 8];
        *(float4*)&op[0] = o0;
        *(float4*)&op[4] = o1;
    }
}

// ---------------- launch ------------------------------------------------------
extern "C" void kernel_launch(void* const* d_in, const int* in_sizes, int n_in,
                              void* d_out, int out_size)
{
    const float* x  = (const float*)d_in[0];
    const float* wq = (const float*)d_in[1];
    const float* wk = (const float*)d_in[2];
    const float* wv = (const float*)d_in[3];
    const float* wo = (const float*)d_in[4];
    float* out = (float*)d_out;

    float* q; cudaGetSymbolAddress((void**)&q, g_q);
    float* k; cudaGetSymbolAddress((void**)&k, g_k);
    float* v; cudaGetSymbolAddress((void**)&v, g_v);
    float* attn; cudaGetSymbolAddress((void**)&attn, g_attn);

    // QKV projections (tf32 wmma)
    gemm_tf32<<<dim3(DIMSZ / 128, MTOK / 128), 256>>>(x, wq, q, DIMSZ, DIMSZ);
    gemm_tf32<<<dim3((NKV * HD) / 128, MTOK / 128), 256>>>(x, wk, k, NKV * HD, DIMSZ);
    gemm_tf32<<<dim3((NKV * HD) / 128, MTOK / 128), 256>>>(x, wv, v, NKV * HD, DIMSZ);

    // RoPE on q and k
    {
        int totq = MTOK * NH * (HD / 2);
        int totk = MTOK * NKV * (HD / 2);
        rope_kernel<<<(totq + 255) / 256, 256>>>(q, NH, totq);
        rope_kernel<<<(totk + 255) / 256, 256>>>(k, NKV, totk);
    }

    // Flash attention
    cudaFuncSetAttribute(attn_kernel, cudaFuncAttributeMaxDynamicSharedMemorySize,
                         ATTN_SMEM_BYTES);
    attn_kernel<<<dim3(SEQ / 64, BATCH * NH), 256, ATTN_SMEM_BYTES>>>(q, k, v, attn);

    // Output projection
    gemm_tf32<<<dim3(DIMSZ / 128, MTOK / 128), 256>>>(attn, wo, out, DIMSZ, DIMSZ);
}

// round 4
// speedup vs baseline: 1.2724x; 1.2724x over previous
#include <cuda_runtime.h>
#include <cuda_bf16.h>
#include <mma.h>
#include <math.h>
#include <cstdint>

using namespace nvcuda;

#define BATCH 2
#define SEQ   2048
#define DIMSZ 4096
#define NH    32
#define NKV   8
#define HD    128
#define MTOK  (BATCH * SEQ)   // 4096 tokens

// ---------------- scratch (static device memory; no allocs allowed) ----------
__device__ float g_q[(size_t)MTOK * NH * HD];     // 67 MB
__device__ float g_k[(size_t)MTOK * NKV * HD];    // 16.8 MB
__device__ float g_v[(size_t)MTOK * NKV * HD];    // 16.8 MB
__device__ float g_attn[(size_t)MTOK * NH * HD];  // 67 MB
__device__ float g_ctab[SEQ * 64];                // rope cos table
__device__ float g_stab[SEQ * 64];                // rope sin table

// ---------------- cp.async helpers -------------------------------------------
__device__ __forceinline__ void cp_async16(float* smem_dst, const float* gmem_src) {
    unsigned int s = (unsigned int)__cvta_generic_to_shared(smem_dst);
    asm volatile("cp.async.cg.shared.global [%0], [%1], 16;\n" :: "r"(s), "l"(gmem_src));
}
__device__ __forceinline__ void cp_commit() {
    asm volatile("cp.async.commit_group;\n" ::: "memory");
}
__device__ __forceinline__ void cp_wait1() {
    asm volatile("cp.async.wait_group 1;\n" ::: "memory");
}
__device__ __forceinline__ void cp_wait0() {
    asm volatile("cp.async.wait_group 0;\n" ::: "memory");
}

// ---------------- tf32 WMMA GEMM: C[M,N] = A[M,K] @ B[K,N], all row-major ----
// Block tile 128x128, K-step 32, 2-stage cp.async pipeline.
// 8 warps in 4x2 grid, each warp 32x64 (2x4 wmma tiles).
#define GA_LD 40    // 128x32 A tile, padded row stride (floats); 160B, mult of 16B
#define GB_LD 136   // 32x128 B tile, padded row stride; 544B, mult of 16B
#define GEMM_STAGE_A (128 * GA_LD)
#define GEMM_STAGE_B (32 * GB_LD)
#define GEMM_SMEM_FLOATS (2 * (GEMM_STAGE_A + GEMM_STAGE_B))
#define GEMM_SMEM_BYTES  (GEMM_SMEM_FLOATS * 4)

__global__ __launch_bounds__(256, 1) void gemm_tf32(
    const float* __restrict__ A, const float* __restrict__ B,
    float* __restrict__ C, int Ndim, int Kdim)
{
    extern __shared__ float gsm[];
    float* AsBase = gsm;                       // 2 x 128 x GA_LD
    float* BsBase = gsm + 2 * GEMM_STAGE_A;    // 2 x 32 x GB_LD

    const int tid = threadIdx.x;
    const int bm = blockIdx.y * 128;
    const int bn = blockIdx.x * 128;
    const int warp = tid >> 5;
    const int wr = warp >> 1;   // 0..3
    const int wc = warp & 1;    // 0..1

    // Per-thread load coordinates (fixed across iterations)
    // A: 1024 float4s -> 4 per thread
    const int ar[4]  = { (tid + 0) >> 3, (tid + 256) >> 3, (tid + 512) >> 3, (tid + 768) >> 3 };
    const int ac4 = (tid & 7) << 2;
    // B: 1024 float4s -> 4 per thread
    const int br[4]  = { (tid + 0) >> 5, (tid + 256) >> 5, (tid + 512) >> 5, (tid + 768) >> 5 };
    const int bc4 = (tid & 31) << 2;

    wmma::fragment<wmma::accumulator, 16, 16, 8, float> acc[2][4];
#pragma unroll
    for (int i = 0; i < 2; i++)
#pragma unroll
        for (int j = 0; j < 4; j++)
            wmma::fill_fragment(acc[i][j], 0.0f);

    const int niter = Kdim >> 5;

    // Prologue: stage 0 loads
    {
        float* As = AsBase;
        float* Bs = BsBase;
#pragma unroll
        for (int i = 0; i < 4; i++)
            cp_async16(&As[ar[i] * GA_LD + ac4], &A[(size_t)(bm + ar[i]) * Kdim + ac4]);
#pragma unroll
        for (int i = 0; i < 4; i++)
            cp_async16(&Bs[br[i] * GB_LD + bc4], &B[(size_t)br[i] * Ndim + bn + bc4]);
        cp_commit();
    }

    for (int it = 0; it < niter; it++) {
        // Issue next stage's loads (overlap with this stage's compute)
        if (it + 1 < niter) {
            const int k0 = (it + 1) << 5;
            float* As = AsBase + ((it + 1) & 1) * GEMM_STAGE_A;
            float* Bs = BsBase + ((it + 1) & 1) * GEMM_STAGE_B;
#pragma unroll
            for (int i = 0; i < 4; i++)
                cp_async16(&As[ar[i] * GA_LD + ac4], &A[(size_t)(bm + ar[i]) * Kdim + k0 + ac4]);
#pragma unroll
            for (int i = 0; i < 4; i++)
                cp_async16(&Bs[br[i] * GB_LD + bc4], &B[(size_t)(k0 + br[i]) * Ndim + bn + bc4]);
            cp_commit();
            cp_wait1();
        } else {
            cp_wait0();
        }
        __syncthreads();

        const float* As = AsBase + (it & 1) * GEMM_STAGE_A;
        const float* Bs = BsBase + (it & 1) * GEMM_STAGE_B;

#pragma unroll
        for (int kk = 0; kk < 32; kk += 8) {
            wmma::fragment<wmma::matrix_a, 16, 16, 8, wmma::precision::tf32, wmma::row_major> af[2];
            wmma::fragment<wmma::matrix_b, 16, 16, 8, wmma::precision::tf32, wmma::row_major> bf[4];
#pragma unroll
            for (int i = 0; i < 2; i++) {
                wmma::load_matrix_sync(af[i], &As[(wr * 32 + i * 16) * GA_LD + kk], GA_LD);
                for (int t = 0; t < af[i].num_elements; t++)
                    af[i].x[t] = wmma::__float_to_tf32(af[i].x[t]);
            }
#pragma unroll
            for (int j = 0; j < 4; j++) {
                wmma::load_matrix_sync(bf[j], &Bs[kk * GB_LD + wc * 64 + j * 16], GB_LD);
                for (int t = 0; t < bf[j].num_elements; t++)
                    bf[j].x[t] = wmma::__float_to_tf32(bf[j].x[t]);
            }
#pragma unroll
            for (int i = 0; i < 2; i++)
#pragma unroll
                for (int j = 0; j < 4; j++)
                    wmma::mma_sync(acc[i][j], af[i], bf[j], acc[i][j]);
        }
        __syncthreads();
    }

#pragma unroll
    for (int i = 0; i < 2; i++)
#pragma unroll
        for (int j = 0; j < 4; j++)
            wmma::store_matrix_sync(
                &C[(size_t)(bm + wr * 32 + i * 16) * Ndim + bn + wc * 64 + j * 16],
                acc[i][j], Ndim, wmma::mem_row_major);
}

// ---------------- RoPE: precompute table (fp64 once), then cheap apply -------
__global__ void rope_table_kernel()
{
    int idx = blockIdx.x * blockDim.x + threadIdx.x;
    if (idx >= SEQ * 64) return;
    int pos = idx >> 6;
    int p = idx & 63;
    // inv = theta^(-2p/128); angle computed like reference (fp32 pos*inv),
    // then reduced mod 2pi in fp64 so sin/cos stay accurate even under fast-math.
    double inv = exp(((double)(-2 * p) / 128.0) * log(500000.0));
    float angf = (float)pos * (float)inv;
    double ar = fmod((double)angf, 6.283185307179586476925287);
    float fa = (float)ar;
    g_ctab[idx] = cosf(fa);
    g_stab[idx] = sinf(fa);
}

__global__ void rope_apply_kernel(float* __restrict__ t, int nheads, int total)
{
    int idx = blockIdx.x * blockDim.x + threadIdx.x;
    if (idx >= total) return;
    int p = idx & 63;            // pair index 0..63
    int rest = idx >> 6;
    int tok = rest / nheads;
    int pos = tok & (SEQ - 1);   // position within sequence

    float c = g_ctab[pos * 64 + p];
    float s = g_stab[pos * 64 + p];

    float2* base = (float2*)(t + (size_t)rest * HD + 2 * p);
    float2 ab = *base;
    float2 o;
    o.x = ab.x * c - ab.y * s;
    o.y = ab.x * s + ab.y * c;
    *base = o;
}

// ---------------- fp32 SIMT flash attention ----------------------------------
// grid (32 q-tiles, 64 batch*head), block 256.
// Q/K/V tiles 64x128 in smem (stride 132), S tile 64x64 (stride 65).
#define QK_LD 132
#define S_LD  65
#define ATTN_SMEM_FLOATS (3 * 64 * QK_LD + 64 * S_LD + 3 * 64)
#define ATTN_SMEM_BYTES  (ATTN_SMEM_FLOATS * 4)

__global__ __launch_bounds__(256, 1) void attn_kernel(
    const float* __restrict__ q, const float* __restrict__ k,
    const float* __restrict__ v, float* __restrict__ o)
{
    extern __shared__ float sm[];
    float* Qs = sm;                     // 64 x 132
    float* Ks = Qs + 64 * QK_LD;        // 64 x 132
    float* Vs = Ks + 64 * QK_LD;        // 64 x 132
    float* Ss = Vs + 64 * QK_LD;        // 64 x 65
    float* rowm = Ss + 64 * S_LD;       // 64 running max
    float* rowl = rowm + 64;            // 64 running sum
    float* salpha = rowl + 64;          // 64 rescale factors

    const int tid = threadIdx.x;
    const int tx = tid & 15;
    const int ty = tid >> 4;
    const int qtile = blockIdx.x;
    const int bh = blockIdx.y;
    const int b = bh / NH;
    const int h = bh % NH;
    const int kvh = h / (NH / NKV);
    const float scale = 0.08838834764831845f;  // 1/sqrt(128)

    // Load Q tile (pre-scaled)
#pragma unroll
    for (int i = 0; i < 8; i++) {
        int fid = tid + i * 256;        // 2048 float4s total
        int r = fid >> 5;
        int c4 = (fid & 31) << 2;
        int sq = qtile * 64 + r;
        float4 vq = *(const float4*)&q[(((size_t)(b * SEQ + sq)) * NH + h) * HD + c4];
        vq.x *= scale; vq.y *= scale; vq.z *= scale; vq.w *= scale;
        *(float4*)&Qs[r * QK_LD + c4] = vq;
    }
    if (tid < 64) { rowm[tid] = -INFINITY; rowl[tid] = 0.0f; }

    float Oacc[4][8];
#pragma unroll
    for (int i = 0; i < 4; i++)
#pragma unroll
        for (int cc = 0; cc < 8; cc++) Oacc[i][cc] = 0.0f;
    __syncthreads();

    for (int kt = 0; kt <= qtile; kt++) {
        // Load K and V tiles
#pragma unroll
        for (int i = 0; i < 8; i++) {
            int fid = tid + i * 256;
            int r = fid >> 5;
            int c4 = (fid & 31) << 2;
            int sk = kt * 64 + r;
            size_t gidx = (((size_t)(b * SEQ + sk)) * NKV + kvh) * HD + c4;
            *(float4*)&Ks[r * QK_LD + c4] = *(const float4*)&k[gidx];
            *(float4*)&Vs[r * QK_LD + c4] = *(const float4*)&v[gidx];
        }
        __syncthreads();

        // S = Q @ K^T  (64x64); thread (tx,ty) owns rows ty+16i, cols tx+16j
        float racc[4][4];
#pragma unroll
        for (int i = 0; i < 4; i++)
#pragma unroll
            for (int j = 0; j < 4; j++) racc[i][j] = 0.0f;

        for (int d4 = 0; d4 < 32; d4++) {
            float4 qv[4], kv[4];
#pragma unroll
            for (int i = 0; i < 4; i++)
                qv[i] = *(const float4*)&Qs[(ty + 16 * i) * QK_LD + d4 * 4];
#pragma unroll
            for (int j = 0; j < 4; j++)
                kv[j] = *(const float4*)&Ks[(tx + 16 * j) * QK_LD + d4 * 4];
#pragma unroll
            for (int i = 0; i < 4; i++)
#pragma unroll
                for (int j = 0; j < 4; j++) {
                    racc[i][j] += qv[i].x * kv[j].x;
                    racc[i][j] += qv[i].y * kv[j].y;
                    racc[i][j] += qv[i].z * kv[j].z;
                    racc[i][j] += qv[i].w * kv[j].w;
                }
        }

        const bool diag = (kt == qtile);
#pragma unroll
        for (int i = 0; i < 4; i++)
#pragma unroll
            for (int j = 0; j < 4; j++) {
                int r = ty + 16 * i, c = tx + 16 * j;
                float val = racc[i][j];
                if (diag && c > r) val = -1e9f;
                Ss[r * S_LD + c] = val;
            }
        __syncthreads();

        // Online softmax stats
        if (tid < 64) {
            float mold = rowm[tid];
            float mx = mold;
            const float* sr = &Ss[tid * S_LD];
#pragma unroll 8
            for (int c = 0; c < 64; c++) mx = fmaxf(mx, sr[c]);
            rowm[tid] = mx;
            salpha[tid] = __expf(mold - mx);  // 0 on first tile (mold=-inf)
        }
        __syncthreads();

        // Exponentiate in place
        for (int idx2 = tid; idx2 < 4096; idx2 += 256) {
            int r = idx2 >> 6, c = idx2 & 63;
            Ss[r * S_LD + c] = __expf(Ss[r * S_LD + c] - rowm[r]);
        }
        __syncthreads();

        // Row sums -> running l
        if (tid < 64) {
            float ssum = 0.0f;
            const float* sr = &Ss[tid * S_LD];
#pragma unroll 8
            for (int c = 0; c < 64; c++) ssum += sr[c];
            rowl[tid] = rowl[tid] * salpha[tid] + ssum;
        }

        // O = O*alpha + P @ V ; thread owns rows ty+16i, cols tx*8..tx*8+7
#pragma unroll
        for (int i = 0; i < 4; i++) {
            float a = salpha[ty + 16 * i];
#pragma unroll
            for (int cc = 0; cc < 8; cc++) Oacc[i][cc] *= a;
        }
        for (int c = 0; c < 64; c++) {
            float pv[4];
#pragma unroll
            for (int i = 0; i < 4; i++) pv[i] = Ss[(ty + 16 * i) * S_LD + c];
            float4 v0 = *(const float4*)&Vs[c * QK_LD + tx * 8];
            float4 v1 = *(const float4*)&Vs[c * QK_LD + tx * 8 + 4];
#pragma unroll
            for (int i = 0; i < 4; i++) {
                Oacc[i][0] += pv[i] * v0.x;
                Oacc[i][1] += pv[i] * v0.y;
                Oacc[i][2] += pv[i] * v0.z;
                Oacc[i][3] += pv[i] * v0.w;
                Oacc[i][4] += pv[i] * v1.x;
                Oacc[i][5] += pv[i] * v1.y;
                Oacc[i][6] += pv[i] * v1.z;
                Oacc[i][7] += pv[i] * v1.w;
            }
        }
        __syncthreads();
    }

    // Write normalized output
#pragma unroll
    for (int i = 0; i < 4; i++) {
        int r = ty + 16 * i;
        int sq = qtile * 64 + r;
        float invl = 1.0f / rowl[r];
        float4 o0, o1;
        o0.x = Oacc[i][0] * invl; o0.y = Oacc[i][1] * invl;
        o0.z = Oacc[i][2] * invl; o0.w = Oacc[i][3] * invl;
        o1.x = Oacc[i][4] * invl; o1.y = Oacc[i][5] * invl;
        o1.z = Oacc[i][6] * invl; o1.w = Oacc[i][7] * invl;
        float* op = &o[(((size_t)(b * SEQ + sq)) * NH + h) * HD + tx * 8];
        *(float4*)&op[0] = o0;
        *(float4*)&op[4] = o1;
    }
}

// ---------------- launch ------------------------------------------------------
extern "C" void kernel_launch(void* const* d_in, const int* in_sizes, int n_in,
                              void* d_out, int out_size)
{
    const float* x  = (const float*)d_in[0];
    const float* wq = (const float*)d_in[1];
    const float* wk = (const float*)d_in[2];
    const float* wv = (const float*)d_in[3];
    const float* wo = (const float*)d_in[4];
    float* out = (float*)d_out;

    float* q; cudaGetSymbolAddress((void**)&q, g_q);
    float* k; cudaGetSymbolAddress((void**)&k, g_k);
    float* v; cudaGetSymbolAddress((void**)&v, g_v);
    float* attn; cudaGetSymbolAddress((void**)&attn, g_attn);

    cudaFuncSetAttribute(gemm_tf32, cudaFuncAttributeMaxDynamicSharedMemorySize,
                         GEMM_SMEM_BYTES);
    cudaFuncSetAttribute(attn_kernel, cudaFuncAttributeMaxDynamicSharedMemorySize,
                         ATTN_SMEM_BYTES);

    // RoPE table (cheap)
    rope_table_kernel<<<(SEQ * 64 + 255) / 256, 256>>>();

    // QKV projections (tf32 wmma, 2-stage cp.async)
    gemm_tf32<<<dim3(DIMSZ / 128, MTOK / 128), 256, GEMM_SMEM_BYTES>>>(x, wq, q, DIMSZ, DIMSZ);
    gemm_tf32<<<dim3((NKV * HD) / 128, MTOK / 128), 256, GEMM_SMEM_BYTES>>>(x, wk, k, NKV * HD, DIMSZ);
    gemm_tf32<<<dim3((NKV * HD) / 128, MTOK / 128), 256, GEMM_SMEM_BYTES>>>(x, wv, v, NKV * HD, DIMSZ);

    // RoPE on q and k (table-based, memory-bound)
    {
        int totq = MTOK * NH * (HD / 2);
        int totk = MTOK * NKV * (HD / 2);
        rope_apply_kernel<<<(totq + 255) / 256, 256>>>(q, NH, totq);
        rope_apply_kernel<<<(totk + 255) / 256, 256>>>(k, NKV, totk);
    }

    // Flash attention
    attn_kernel<<<dim3(SEQ / 64, BATCH * NH), 256, ATTN_SMEM_BYTES>>>(q, k, v, attn);

    // Output projection
    gemm_tf32<<<dim3(DIMSZ / 128, MTOK / 128), 256, GEMM_SMEM_BYTES>>>(attn, wo, out, DIMSZ, DIMSZ);
}

// round 7
// speedup vs baseline: 1.3084x; 1.0283x over previous
// Round 7 resubmission of the Round-5/6 kernel (broker failed twice; no signal).
#include <cuda_runtime.h>
#include <cuda_bf16.h>
#include <mma.h>
#include <math.h>
#include <cstdint>

using namespace nvcuda;

#define BATCH 2
#define SEQ   2048
#define DIMSZ 4096
#define NH    32
#define NKV   8
#define HD    128
#define MTOK  (BATCH * SEQ)   // 4096 tokens

// ---------------- scratch (static device memory; no allocs allowed) ----------
__device__ float g_q[(size_t)MTOK * NH * HD];     // 67 MB
__device__ float g_k[(size_t)MTOK * NKV * HD];    // 16.8 MB
__device__ float g_v[(size_t)MTOK * NKV * HD];    // 16.8 MB
__device__ float g_attn[(size_t)MTOK * NH * HD];  // 67 MB
__device__ float g_ctab[SEQ * 64];                // rope cos table
__device__ float g_stab[SEQ * 64];                // rope sin table

// ---------------- cp.async helpers -------------------------------------------
__device__ __forceinline__ void cp_async16(float* smem_dst, const float* gmem_src) {
    unsigned int s = (unsigned int)__cvta_generic_to_shared(smem_dst);
    asm volatile("cp.async.cg.shared.global [%0], [%1], 16;\n" :: "r"(s), "l"(gmem_src));
}
__device__ __forceinline__ void cp_commit() {
    asm volatile("cp.async.commit_group;\n" ::: "memory");
}
__device__ __forceinline__ void cp_wait1() {
    asm volatile("cp.async.wait_group 1;\n" ::: "memory");
}
__device__ __forceinline__ void cp_wait0() {
    asm volatile("cp.async.wait_group 0;\n" ::: "memory");
}

// ---------------- tf32 WMMA GEMM core: C[128,128] tile of A[M,K]@B[K,N] ------
// Block tile 128x128, K-step 32, 2-stage cp.async pipeline.
// 8 warps in 4x2 grid, each warp 32x64 (2x4 wmma tiles).
#define GA_LD 40    // 128x32 A tile, padded row stride (floats)
#define GB_LD 136   // 32x128 B tile, padded row stride
#define GEMM_STAGE_A (128 * GA_LD)
#define GEMM_STAGE_B (32 * GB_LD)
#define GEMM_SMEM_FLOATS (2 * (GEMM_STAGE_A + GEMM_STAGE_B))
#define GEMM_SMEM_BYTES  (GEMM_SMEM_FLOATS * 4)

__device__ __forceinline__ void gemm_core(
    const float* __restrict__ A, const float* __restrict__ B,
    float* __restrict__ C, int Ndim, int Kdim, int bm, int bn, float* gsm)
{
    float* AsBase = gsm;                       // 2 x 128 x GA_LD
    float* BsBase = gsm + 2 * GEMM_STAGE_A;    // 2 x 32 x GB_LD

    const int tid = threadIdx.x;
    const int warp = tid >> 5;
    const int wr = warp >> 1;   // 0..3
    const int wc = warp & 1;    // 0..1

    // Per-thread load coordinates (fixed across iterations)
    const int ar0 = tid >> 3;            // +32 per chunk
    const int ac4 = (tid & 7) << 2;
    const int br0 = tid >> 5;            // +8 per chunk
    const int bc4 = (tid & 31) << 2;

    wmma::fragment<wmma::accumulator, 16, 16, 8, float> acc[2][4];
#pragma unroll
    for (int i = 0; i < 2; i++)
#pragma unroll
        for (int j = 0; j < 4; j++)
            wmma::fill_fragment(acc[i][j], 0.0f);

    const int niter = Kdim >> 5;

    // Prologue: stage 0 loads
    {
        float* As = AsBase;
        float* Bs = BsBase;
#pragma unroll
        for (int i = 0; i < 4; i++)
            cp_async16(&As[(ar0 + 32 * i) * GA_LD + ac4],
                       &A[(size_t)(bm + ar0 + 32 * i) * Kdim + ac4]);
#pragma unroll
        for (int i = 0; i < 4; i++)
            cp_async16(&Bs[(br0 + 8 * i) * GB_LD + bc4],
                       &B[(size_t)(br0 + 8 * i) * Ndim + bn + bc4]);
        cp_commit();
    }

    for (int it = 0; it < niter; it++) {
        // Issue next stage's loads (overlap with this stage's compute)
        if (it + 1 < niter) {
            const int k0 = (it + 1) << 5;
            float* As = AsBase + ((it + 1) & 1) * GEMM_STAGE_A;
            float* Bs = BsBase + ((it + 1) & 1) * GEMM_STAGE_B;
#pragma unroll
            for (int i = 0; i < 4; i++)
                cp_async16(&As[(ar0 + 32 * i) * GA_LD + ac4],
                           &A[(size_t)(bm + ar0 + 32 * i) * Kdim + k0 + ac4]);
#pragma unroll
            for (int i = 0; i < 4; i++)
                cp_async16(&Bs[(br0 + 8 * i) * GB_LD + bc4],
                           &B[(size_t)(k0 + br0 + 8 * i) * Ndim + bn + bc4]);
            cp_commit();
            cp_wait1();
        } else {
            cp_wait0();
        }
        __syncthreads();

        const float* As = AsBase + (it & 1) * GEMM_STAGE_A;
        const float* Bs = BsBase + (it & 1) * GEMM_STAGE_B;

#pragma unroll
        for (int kk = 0; kk < 32; kk += 8) {
            wmma::fragment<wmma::matrix_a, 16, 16, 8, wmma::precision::tf32, wmma::row_major> af[2];
            wmma::fragment<wmma::matrix_b, 16, 16, 8, wmma::precision::tf32, wmma::row_major> bf[4];
#pragma unroll
            for (int i = 0; i < 2; i++) {
                wmma::load_matrix_sync(af[i], &As[(wr * 32 + i * 16) * GA_LD + kk], GA_LD);
                for (int t = 0; t < af[i].num_elements; t++)
                    af[i].x[t] = wmma::__float_to_tf32(af[i].x[t]);
            }
#pragma unroll
            for (int j = 0; j < 4; j++) {
                wmma::load_matrix_sync(bf[j], &Bs[kk * GB_LD + wc * 64 + j * 16], GB_LD);
                for (int t = 0; t < bf[j].num_elements; t++)
                    bf[j].x[t] = wmma::__float_to_tf32(bf[j].x[t]);
            }
#pragma unroll
            for (int i = 0; i < 2; i++)
#pragma unroll
                for (int j = 0; j < 4; j++)
                    wmma::mma_sync(acc[i][j], af[i], bf[j], acc[i][j]);
        }
        __syncthreads();
    }

#pragma unroll
    for (int i = 0; i < 2; i++)
#pragma unroll
        for (int j = 0; j < 4; j++)
            wmma::store_matrix_sync(
                &C[(size_t)(bm + wr * 32 + i * 16) * Ndim + bn + wc * 64 + j * 16],
                acc[i][j], Ndim, wmma::mem_row_major);
}

// Plain GEMM (used for output projection)
__global__ __launch_bounds__(256, 2) void gemm_tf32(
    const float* __restrict__ A, const float* __restrict__ B,
    float* __restrict__ C, int Ndim, int Kdim)
{
    extern __shared__ float gsm[];
    gemm_core(A, B, C, Ndim, Kdim, blockIdx.y * 128, blockIdx.x * 128, gsm);
}

// Fused QKV projection: one launch covers wq|wk|wv columns (N = 4096+1024+1024)
__global__ __launch_bounds__(256, 2) void gemm_qkv_tf32(
    const float* __restrict__ x,
    const float* __restrict__ wq, const float* __restrict__ wk,
    const float* __restrict__ wv,
    float* __restrict__ q, float* __restrict__ k, float* __restrict__ v)
{
    extern __shared__ float gsm[];
    const int bnTot = blockIdx.x * 128;
    const float* W;
    float* Out;
    int Nw, bn;
    if (bnTot < NH * HD)            { W = wq; Out = q; Nw = NH * HD;  bn = bnTot; }
    else if (bnTot < NH * HD + NKV * HD) { W = wk; Out = k; Nw = NKV * HD; bn = bnTot - NH * HD; }
    else                            { W = wv; Out = v; Nw = NKV * HD; bn = bnTot - NH * HD - NKV * HD; }
    gemm_core(x, W, Out, Nw, DIMSZ, blockIdx.y * 128, bn, gsm);
}

// ---------------- RoPE: precompute table (fp64 once), then cheap apply -------
__global__ void rope_table_kernel()
{
    int idx = blockIdx.x * blockDim.x + threadIdx.x;
    if (idx >= SEQ * 64) return;
    int pos = idx >> 6;
    int p = idx & 63;
    // inv = theta^(-2p/128); angle computed like reference (fp32 pos*inv),
    // then reduced mod 2pi in fp64 so sin/cos stay accurate even under fast-math.
    double inv = exp(((double)(-2 * p) / 128.0) * log(500000.0));
    float angf = (float)pos * (float)inv;
    double ar = fmod((double)angf, 6.283185307179586476925287);
    float fa = (float)ar;
    g_ctab[idx] = cosf(fa);
    g_stab[idx] = sinf(fa);
}

__global__ void rope_apply_kernel(float* __restrict__ t, int nheads, int total)
{
    int idx = blockIdx.x * blockDim.x + threadIdx.x;
    if (idx >= total) return;
    int p = idx & 63;            // pair index 0..63
    int rest = idx >> 6;
    int tok = rest / nheads;
    int pos = tok & (SEQ - 1);   // position within sequence

    float c = g_ctab[pos * 64 + p];
    float s = g_stab[pos * 64 + p];

    float2* base = (float2*)(t + (size_t)rest * HD + 2 * p);
    float2 ab = *base;
    float2 o;
    o.x = ab.x * c - ab.y * s;
    o.y = ab.x * s + ab.y * c;
    *base = o;
}

// ---------------- fp32 SIMT flash attention ----------------------------------
// grid (32 q-tiles, 64 batch*head), block 256.
#define QK_LD 132
#define S_LD  65
#define ATTN_SMEM_FLOATS (3 * 64 * QK_LD + 64 * S_LD + 3 * 64)
#define ATTN_SMEM_BYTES  (ATTN_SMEM_FLOATS * 4)

__global__ __launch_bounds__(256, 1) void attn_kernel(
    const float* __restrict__ q, const float* __restrict__ k,
    const float* __restrict__ v, float* __restrict__ o)
{
    extern __shared__ float sm[];
    float* Qs = sm;                     // 64 x 132
    float* Ks = Qs + 64 * QK_LD;        // 64 x 132
    float* Vs = Ks + 64 * QK_LD;        // 64 x 132
    float* Ss = Vs + 64 * QK_LD;        // 64 x 65
    float* rowm = Ss + 64 * S_LD;       // 64 running max
    float* rowl = rowm + 64;            // 64 running sum
    float* salpha = rowl + 64;          // 64 rescale factors

    const int tid = threadIdx.x;
    const int tx = tid & 15;
    const int ty = tid >> 4;
    const int qtile = blockIdx.x;
    const int bh = blockIdx.y;
    const int b = bh / NH;
    const int h = bh % NH;
    const int kvh = h / (NH / NKV);
    const float scale = 0.08838834764831845f;  // 1/sqrt(128)

    // Load Q tile (pre-scaled)
#pragma unroll
    for (int i = 0; i < 8; i++) {
        int fid = tid + i * 256;        // 2048 float4s total
        int r = fid >> 5;
        int c4 = (fid & 31) << 2;
        int sq = qtile * 64 + r;
        float4 vq = *(const float4*)&q[(((size_t)(b * SEQ + sq)) * NH + h) * HD + c4];
        vq.x *= scale; vq.y *= scale; vq.z *= scale; vq.w *= scale;
        *(float4*)&Qs[r * QK_LD + c4] = vq;
    }
    if (tid < 64) { rowm[tid] = -INFINITY; rowl[tid] = 0.0f; }

    float Oacc[4][8];
#pragma unroll
    for (int i = 0; i < 4; i++)
#pragma unroll
        for (int cc = 0; cc < 8; cc++) Oacc[i][cc] = 0.0f;
    __syncthreads();

    for (int kt = 0; kt <= qtile; kt++) {
        // Load K and V tiles
#pragma unroll
        for (int i = 0; i < 8; i++) {
            int fid = tid + i * 256;
            int r = fid >> 5;
            int c4 = (fid & 31) << 2;
            int sk = kt * 64 + r;
            size_t gidx = (((size_t)(b * SEQ + sk)) * NKV + kvh) * HD + c4;
            *(float4*)&Ks[r * QK_LD + c4] = *(const float4*)&k[gidx];
            *(float4*)&Vs[r * QK_LD + c4] = *(const float4*)&v[gidx];
        }
        __syncthreads();

        // S = Q @ K^T  (64x64); thread (tx,ty) owns rows ty+16i, cols tx+16j
        float racc[4][4];
#pragma unroll
        for (int i = 0; i < 4; i++)
#pragma unroll
            for (int j = 0; j < 4; j++) racc[i][j] = 0.0f;

        for (int d4 = 0; d4 < 32; d4++) {
            float4 qv[4], kv[4];
#pragma unroll
            for (int i = 0; i < 4; i++)
                qv[i] = *(const float4*)&Qs[(ty + 16 * i) * QK_LD + d4 * 4];
#pragma unroll
            for (int j = 0; j < 4; j++)
                kv[j] = *(const float4*)&Ks[(tx + 16 * j) * QK_LD + d4 * 4];
#pragma unroll
            for (int i = 0; i < 4; i++)
#pragma unroll
                for (int j = 0; j < 4; j++) {
                    racc[i][j] += qv[i].x * kv[j].x;
                    racc[i][j] += qv[i].y * kv[j].y;
                    racc[i][j] += qv[i].z * kv[j].z;
                    racc[i][j] += qv[i].w * kv[j].w;
                }
        }

        const bool diag = (kt == qtile);
#pragma unroll
        for (int i = 0; i < 4; i++)
#pragma unroll
            for (int j = 0; j < 4; j++) {
                int r = ty + 16 * i, c = tx + 16 * j;
                float val = racc[i][j];
                if (diag && c > r) val = -1e9f;
                Ss[r * S_LD + c] = val;
            }
        __syncthreads();

        // Online softmax stats
        if (tid < 64) {
            float mold = rowm[tid];
            float mx = mold;
            const float* sr = &Ss[tid * S_LD];
#pragma unroll 8
            for (int c = 0; c < 64; c++) mx = fmaxf(mx, sr[c]);
            rowm[tid] = mx;
            salpha[tid] = __expf(mold - mx);  // 0 on first tile (mold=-inf)
        }
        __syncthreads();

        // Exponentiate in place
        for (int idx2 = tid; idx2 < 4096; idx2 += 256) {
            int r = idx2 >> 6, c = idx2 & 63;
            Ss[r * S_LD + c] = __expf(Ss[r * S_LD + c] - rowm[r]);
        }
        __syncthreads();

        // Row sums -> running l
        if (tid < 64) {
            float ssum = 0.0f;
            const float* sr = &Ss[tid * S_LD];
#pragma unroll 8
            for (int c = 0; c < 64; c++) ssum += sr[c];
            rowl[tid] = rowl[tid] * salpha[tid] + ssum;
        }

        // O = O*alpha + P @ V ; thread owns rows ty+16i, cols tx*8..tx*8+7
#pragma unroll
        for (int i = 0; i < 4; i++) {
            float a = salpha[ty + 16 * i];
#pragma unroll
            for (int cc = 0; cc < 8; cc++) Oacc[i][cc] *= a;
        }
        for (int c = 0; c < 64; c++) {
            float pv[4];
#pragma unroll
            for (int i = 0; i < 4; i++) pv[i] = Ss[(ty + 16 * i) * S_LD + c];
            float4 v0 = *(const float4*)&Vs[c * QK_LD + tx * 8];
            float4 v1 = *(const float4*)&Vs[c * QK_LD + tx * 8 + 4];
#pragma unroll
            for (int i = 0; i < 4; i++) {
                Oacc[i][0] += pv[i] * v0.x;
                Oacc[i][1] += pv[i] * v0.y;
                Oacc[i][2] += pv[i] * v0.z;
                Oacc[i][3] += pv[i] * v0.w;
                Oacc[i][4] += pv[i] * v1.x;
                Oacc[i][5] += pv[i] * v1.y;
                Oacc[i][6] += pv[i] * v1.z;
                Oacc[i][7] += pv[i] * v1.w;
            }
        }
        __syncthreads();
    }

    // Write normalized output
#pragma unroll
    for (int i = 0; i < 4; i++) {
        int r = ty + 16 * i;
        int sq = qtile * 64 + r;
        float invl = 1.0f / rowl[r];
        float4 o0, o1;
        o0.x = Oacc[i][0] * invl; o0.y = Oacc[i][1] * invl;
        o0.z = Oacc[i][2] * invl; o0.w = Oacc[i][3] * invl;
        o1.x = Oacc[i][4] * invl; o1.y = Oacc[i][5] * invl;
        o1.z = Oacc[i][6] * invl; o1.w = Oacc[i][7] * invl;
        float* op = &o[(((size_t)(b * SEQ + sq)) * NH + h) * HD + tx * 8];
        *(float4*)&op[0] = o0;
        *(float4*)&op[4] = o1;
    }
}

// ---------------- launch ------------------------------------------------------
extern "C" void kernel_launch(void* const* d_in, const int* in_sizes, int n_in,
                              void* d_out, int out_size)
{
    const float* x  = (const float*)d_in[0];
    const float* wq = (const float*)d_in[1];
    const float* wk = (const float*)d_in[2];
    const float* wv = (const float*)d_in[3];
    const float* wo = (const float*)d_in[4];
    float* out = (float*)d_out;

    float* q; cudaGetSymbolAddress((void**)&q, g_q);
    float* k; cudaGetSymbolAddress((void**)&k, g_k);
    float* v; cudaGetSymbolAddress((void**)&v, g_v);
    float* attn; cudaGetSymbolAddress((void**)&attn, g_attn);

    cudaFuncSetAttribute(gemm_tf32, cudaFuncAttributeMaxDynamicSharedMemorySize,
                         GEMM_SMEM_BYTES);
    cudaFuncSetAttribute(gemm_qkv_tf32, cudaFuncAttributeMaxDynamicSharedMemorySize,
                         GEMM_SMEM_BYTES);
    cudaFuncSetAttribute(attn_kernel, cudaFuncAttributeMaxDynamicSharedMemorySize,
                         ATTN_SMEM_BYTES);

    // RoPE table (cheap)
    rope_table_kernel<<<(SEQ * 64 + 255) / 256, 256>>>();

    // Fused QKV projection (tf32 wmma, 2-stage cp.async, 2 CTAs/SM)
    gemm_qkv_tf32<<<dim3((NH * HD + 2 * NKV * HD) / 128, MTOK / 128), 256,
                    GEMM_SMEM_BYTES>>>(x, wq, wk, wv, q, k, v);

    // RoPE on q and k (table-based, memory-bound)
    {
        int totq = MTOK * NH * (HD / 2);
        int totk = MTOK * NKV * (HD / 2);
        rope_apply_kernel<<<(totq + 255) / 256, 256>>>(q, NH, totq);
        rope_apply_kernel<<<(totk + 255) / 256, 256>>>(k, NKV, totk);
    }

    // Flash attention
    attn_kernel<<<dim3(SEQ / 64, BATCH * NH), 256, ATTN_SMEM_BYTES>>>(q, k, v, attn);

    // Output projection
    gemm_tf32<<<dim3(DIMSZ / 128, MTOK / 128), 256, GEMM_SMEM_BYTES>>>(attn, wo, out, DIMSZ, DIMSZ);
}

// round 11
// speedup vs baseline: 1.9860x; 1.5179x over previous
// Round 10: fp16 WMMA GEMMs (tf32-equivalent 10-bit mantissa, 2x HMMA rate,
// LDSM fragments, convert-at-STS) + fp32 SIMT flash attention.
// tcgen05 is unusable: harness PTX targets sm_103 (no 'a' feature suffix).
#include <cuda_runtime.h>
#include <cuda_fp16.h>
#include <mma.h>
#include <math.h>
#include <cstdint>

using namespace nvcuda;

#define BATCH 2
#define SEQ   2048
#define DIMSZ 4096
#define NH    32
#define NKV   8
#define HD    128
#define MTOK  (BATCH * SEQ)   // 4096 tokens

// ---------------- scratch (static device memory; no allocs allowed) ----------
__device__ float g_q[(size_t)MTOK * NH * HD];     // 67 MB
__device__ float g_k[(size_t)MTOK * NKV * HD];    // 16.8 MB
__device__ float g_v[(size_t)MTOK * NKV * HD];    // 16.8 MB
__device__ float g_attn[(size_t)MTOK * NH * HD];  // 67 MB
__device__ float g_ctab[SEQ * 64];                // rope cos table
__device__ float g_stab[SEQ * 64];                // rope sin table

// ---------------- fp16 WMMA GEMM: C[M,N] = A[M,K] @ B[K,N], row-major --------
// Block 128x128, 512 threads (16 warps, 4x4), warp tile 32x32, K-step 32.
// Register->smem double buffer: LDG next K-chunk into regs during MMA phase.
#define HA_LD 40     // A tile row stride in halfs (32 + 8 pad)
#define HB_LD 136    // B tile row stride in halfs (128 + 8 pad)
#define HSTAGE_A (128 * HA_LD)          // 5120 halfs
#define HSTAGE_B (32 * HB_LD)           // 4352 halfs
#define GEMM_H_SMEM ((2 * (HSTAGE_A + HSTAGE_B)) * 2)   // bytes = 37888

__device__ __forceinline__ void gemm_h_core(
    const float* __restrict__ A, const float* __restrict__ B,
    float* __restrict__ C, int Ndim, int Kdim, int bm, int bn, __half* hsm)
{
    __half* AsBase = hsm;                       // 2 stages of 128 x HA_LD
    __half* BsBase = hsm + 2 * HSTAGE_A;        // 2 stages of 32 x HB_LD

    const int tid  = threadIdx.x;
    const int warp = tid >> 5;
    const int wr = warp >> 2;    // 0..3  (M direction)
    const int wc = warp & 3;     // 0..3  (N direction)

    // A loads: thread -> row tid>>2 (0..127), cols (tid&3)*8 .. +7  (2 float4)
    const int arow = tid >> 2;
    const int acol = (tid & 3) * 8;
    // B loads: thread -> row tid>>4 (0..31), cols (tid&15)*8 .. +7  (2 float4)
    const int brow = tid >> 4;
    const int bcol = (tid & 15) * 8;

    wmma::fragment<wmma::accumulator, 16, 16, 16, float> acc[2][2];
#pragma unroll
    for (int i = 0; i < 2; i++)
#pragma unroll
        for (int j = 0; j < 2; j++)
            wmma::fill_fragment(acc[i][j], 0.0f);

    const int niter = Kdim >> 5;

    float4 a0, a1, b0, b1;
    auto ldg_chunk = [&](int k0) {
        const float* ap = &A[(size_t)(bm + arow) * Kdim + k0 + acol];
        a0 = *(const float4*)ap;
        a1 = *(const float4*)(ap + 4);
        const float* bp = &B[(size_t)(k0 + brow) * Ndim + bn + bcol];
        b0 = *(const float4*)bp;
        b1 = *(const float4*)(bp + 4);
    };
    auto sts_chunk = [&](int stage) {
        __half* As = AsBase + stage * HSTAGE_A;
        __half* Bs = BsBase + stage * HSTAGE_B;
        __half2 p[4];
        p[0] = __floats2half2_rn(a0.x, a0.y);
        p[1] = __floats2half2_rn(a0.z, a0.w);
        p[2] = __floats2half2_rn(a1.x, a1.y);
        p[3] = __floats2half2_rn(a1.z, a1.w);
        *(uint4*)&As[arow * HA_LD + acol] = *(uint4*)p;
        p[0] = __floats2half2_rn(b0.x, b0.y);
        p[1] = __floats2half2_rn(b0.z, b0.w);
        p[2] = __floats2half2_rn(b1.x, b1.y);
        p[3] = __floats2half2_rn(b1.z, b1.w);
        *(uint4*)&Bs[brow * HB_LD + bcol] = *(uint4*)p;
    };

    // Prologue: stage 0
    ldg_chunk(0);
    sts_chunk(0);
    __syncthreads();

    for (int it = 0; it < niter; it++) {
        const bool more = (it + 1 < niter);
        if (more) ldg_chunk((it + 1) << 5);   // overlap with MMA below

        const __half* As = AsBase + (it & 1) * HSTAGE_A;
        const __half* Bs = BsBase + (it & 1) * HSTAGE_B;

#pragma unroll
        for (int kk = 0; kk < 32; kk += 16) {
            wmma::fragment<wmma::matrix_a, 16, 16, 16, __half, wmma::row_major> af[2];
            wmma::fragment<wmma::matrix_b, 16, 16, 16, __half, wmma::row_major> bf[2];
#pragma unroll
            for (int i = 0; i < 2; i++)
                wmma::load_matrix_sync(af[i], &As[(wr * 32 + i * 16) * HA_LD + kk], HA_LD);
#pragma unroll
            for (int j = 0; j < 2; j++)
                wmma::load_matrix_sync(bf[j], &Bs[kk * HB_LD + wc * 32 + j * 16], HB_LD);
#pragma unroll
            for (int i = 0; i < 2; i++)
#pragma unroll
                for (int j = 0; j < 2; j++)
                    wmma::mma_sync(acc[i][j], af[i], bf[j], acc[i][j]);
        }

        if (more) sts_chunk((it + 1) & 1);
        __syncthreads();
    }

#pragma unroll
    for (int i = 0; i < 2; i++)
#pragma unroll
        for (int j = 0; j < 2; j++)
            wmma::store_matrix_sync(
                &C[(size_t)(bm + wr * 32 + i * 16) * Ndim + bn + wc * 32 + j * 16],
                acc[i][j], Ndim, wmma::mem_row_major);
}

// Plain GEMM (output projection)
__global__ __launch_bounds__(512, 1) void gemm_h(
    const float* __restrict__ A, const float* __restrict__ B,
    float* __restrict__ C, int Ndim, int Kdim)
{
    extern __shared__ __half hsm[];
    gemm_h_core(A, B, C, Ndim, Kdim, blockIdx.y * 128, blockIdx.x * 128, hsm);
}

// Fused QKV projection: N-tiles cover wq|wk|wv (4096 + 1024 + 1024)
__global__ __launch_bounds__(512, 1) void gemm_h_qkv(
    const float* __restrict__ x,
    const float* __restrict__ wq, const float* __restrict__ wk,
    const float* __restrict__ wv,
    float* __restrict__ q, float* __restrict__ k, float* __restrict__ v)
{
    extern __shared__ __half hsm[];
    const int bnTot = blockIdx.x * 128;
    const float* W;
    float* Out;
    int Nw, bn;
    if (bnTot < NH * HD)                 { W = wq; Out = q; Nw = NH * HD;  bn = bnTot; }
    else if (bnTot < NH * HD + NKV * HD) { W = wk; Out = k; Nw = NKV * HD; bn = bnTot - NH * HD; }
    else                                 { W = wv; Out = v; Nw = NKV * HD; bn = bnTot - NH * HD - NKV * HD; }
    gemm_h_core(x, W, Out, Nw, DIMSZ, blockIdx.y * 128, bn, hsm);
}

// ---------------- RoPE: precompute table (fp64 once), then cheap apply -------
__global__ void rope_table_kernel()
{
    int idx = blockIdx.x * blockDim.x + threadIdx.x;
    if (idx >= SEQ * 64) return;
    int pos = idx >> 6;
    int p = idx & 63;
    double inv = exp(((double)(-2 * p) / 128.0) * log(500000.0));
    float angf = (float)pos * (float)inv;
    double ar = fmod((double)angf, 6.283185307179586476925287);
    float fa = (float)ar;
    g_ctab[idx] = cosf(fa);
    g_stab[idx] = sinf(fa);
}

__global__ void rope_apply_kernel(float* __restrict__ t, int nheads, int total)
{
    int idx = blockIdx.x * blockDim.x + threadIdx.x;
    if (idx >= total) return;
    int p = idx & 63;
    int rest = idx >> 6;
    int tok = rest / nheads;
    int pos = tok & (SEQ - 1);

    float c = g_ctab[pos * 64 + p];
    float s = g_stab[pos * 64 + p];

    float2* base = (float2*)(t + (size_t)rest * HD + 2 * p);
    float2 ab = *base;
    float2 o;
    o.x = ab.x * c - ab.y * s;
    o.y = ab.x * s + ab.y * c;
    *base = o;
}

// ---------------- fp32 SIMT flash attention (unchanged, known-good) ----------
#define QK_LD 132
#define S_LD  65
#define ATTN_SMEM_FLOATS (3 * 64 * QK_LD + 64 * S_LD + 3 * 64)
#define ATTN_SMEM_BYTES  (ATTN_SMEM_FLOATS * 4)

__global__ __launch_bounds__(256, 1) void attn_kernel(
    const float* __restrict__ q, const float* __restrict__ k,
    const float* __restrict__ v, float* __restrict__ o)
{
    extern __shared__ float sm[];
    float* Qs = sm;
    float* Ks = Qs + 64 * QK_LD;
    float* Vs = Ks + 64 * QK_LD;
    float* Ss = Vs + 64 * QK_LD;
    float* rowm = Ss + 64 * S_LD;
    float* rowl = rowm + 64;
    float* salpha = rowl + 64;

    const int tid = threadIdx.x;
    const int tx = tid & 15;
    const int ty = tid >> 4;
    const int qtile = blockIdx.x;
    const int bh = blockIdx.y;
    const int b = bh / NH;
    const int h = bh % NH;
    const int kvh = h / (NH / NKV);
    const float scale = 0.08838834764831845f;

#pragma unroll
    for (int i = 0; i < 8; i++) {
        int fid = tid + i * 256;
        int r = fid >> 5;
        int c4 = (fid & 31) << 2;
        int sq = qtile * 64 + r;
        float4 vq = *(const float4*)&q[(((size_t)(b * SEQ + sq)) * NH + h) * HD + c4];
        vq.x *= scale; vq.y *= scale; vq.z *= scale; vq.w *= scale;
        *(float4*)&Qs[r * QK_LD + c4] = vq;
    }
    if (tid < 64) { rowm[tid] = -INFINITY; rowl[tid] = 0.0f; }

    float Oacc[4][8];
#pragma unroll
    for (int i = 0; i < 4; i++)
#pragma unroll
        for (int cc = 0; cc < 8; cc++) Oacc[i][cc] = 0.0f;
    __syncthreads();

    for (int kt = 0; kt <= qtile; kt++) {
#pragma unroll
        for (int i = 0; i < 8; i++) {
            int fid = tid + i * 256;
            int r = fid >> 5;
            int c4 = (fid & 31) << 2;
            int sk = kt * 64 + r;
            size_t gidx = (((size_t)(b * SEQ + sk)) * NKV + kvh) * HD + c4;
            *(float4*)&Ks[r * QK_LD + c4] = *(const float4*)&k[gidx];
            *(float4*)&Vs[r * QK_LD + c4] = *(const float4*)&v[gidx];
        }
        __syncthreads();

        float racc[4][4];
#pragma unroll
        for (int i = 0; i < 4; i++)
#pragma unroll
            for (int j = 0; j < 4; j++) racc[i][j] = 0.0f;

        for (int d4 = 0; d4 < 32; d4++) {
            float4 qv[4], kv[4];
#pragma unroll
            for (int i = 0; i < 4; i++)
                qv[i] = *(const float4*)&Qs[(ty + 16 * i) * QK_LD + d4 * 4];
#pragma unroll
            for (int j = 0; j < 4; j++)
                kv[j] = *(const float4*)&Ks[(tx + 16 * j) * QK_LD + d4 * 4];
#pragma unroll
            for (int i = 0; i < 4; i++)
#pragma unroll
                for (int j = 0; j < 4; j++) {
                    racc[i][j] += qv[i].x * kv[j].x;
                    racc[i][j] += qv[i].y * kv[j].y;
                    racc[i][j] += qv[i].z * kv[j].z;
                    racc[i][j] += qv[i].w * kv[j].w;
                }
        }

        const bool diag = (kt == qtile);
#pragma unroll
        for (int i = 0; i < 4; i++)
#pragma unroll
            for (int j = 0; j < 4; j++) {
                int r = ty + 16 * i, c = tx + 16 * j;
                float val = racc[i][j];
                if (diag && c > r) val = -1e9f;
                Ss[r * S_LD + c] = val;
            }
        __syncthreads();

        if (tid < 64) {
            float mold = rowm[tid];
            float mx = mold;
            const float* sr = &Ss[tid * S_LD];
#pragma unroll 8
            for (int c = 0; c < 64; c++) mx = fmaxf(mx, sr[c]);
            rowm[tid] = mx;
            salpha[tid] = __expf(mold - mx);
        }
        __syncthreads();

        for (int idx2 = tid; idx2 < 4096; idx2 += 256) {
            int r = idx2 >> 6, c = idx2 & 63;
            Ss[r * S_LD + c] = __expf(Ss[r * S_LD + c] - rowm[r]);
        }
        __syncthreads();

        if (tid < 64) {
            float ssum = 0.0f;
            const float* sr = &Ss[tid * S_LD];
#pragma unroll 8
            for (int c = 0; c < 64; c++) ssum += sr[c];
            rowl[tid] = rowl[tid] * salpha[tid] + ssum;
        }

#pragma unroll
        for (int i = 0; i < 4; i++) {
            float a = salpha[ty + 16 * i];
#pragma unroll
            for (int cc = 0; cc < 8; cc++) Oacc[i][cc] *= a;
        }
        for (int c = 0; c < 64; c++) {
            float pv[4];
#pragma unroll
            for (int i = 0; i < 4; i++) pv[i] = Ss[(ty + 16 * i) * S_LD + c];
            float4 v0 = *(const float4*)&Vs[c * QK_LD + tx * 8];
            float4 v1 = *(const float4*)&Vs[c * QK_LD + tx * 8 + 4];
#pragma unroll
            for (int i = 0; i < 4; i++) {
                Oacc[i][0] += pv[i] * v0.x;
                Oacc[i][1] += pv[i] * v0.y;
                Oacc[i][2] += pv[i] * v0.z;
                Oacc[i][3] += pv[i] * v0.w;
                Oacc[i][4] += pv[i] * v1.x;
                Oacc[i][5] += pv[i] * v1.y;
                Oacc[i][6] += pv[i] * v1.z;
                Oacc[i][7] += pv[i] * v1.w;
            }
        }
        __syncthreads();
    }

#pragma unroll
    for (int i = 0; i < 4; i++) {
        int r = ty + 16 * i;
        int sq = qtile * 64 + r;
        float invl = 1.0f / rowl[r];
        float4 o0, o1;
        o0.x = Oacc[i][0] * invl; o0.y = Oacc[i][1] * invl;
        o0.z = Oacc[i][2] * invl; o0.w = Oacc[i][3] * invl;
        o1.x = Oacc[i][4] * invl; o1.y = Oacc[i][5] * invl;
        o1.z = Oacc[i][6] * invl; o1.w = Oacc[i][7] * invl;
        float* op = &o[(((size_t)(b * SEQ + sq)) * NH + h) * HD + tx * 8];
        *(float4*)&op[0] = o0;
        *(float4*)&op[4] = o1;
    }
}

// ---------------- launch ------------------------------------------------------
extern "C" void kernel_launch(void* const* d_in, const int* in_sizes, int n_in,
                              void* d_out, int out_size)
{
    const float* x  = (const float*)d_in[0];
    const float* wq = (const float*)d_in[1];
    const float* wk = (const float*)d_in[2];
    const float* wv = (const float*)d_in[3];
    const float* wo = (const float*)d_in[4];
    float* out = (float*)d_out;

    float* q; cudaGetSymbolAddress((void**)&q, g_q);
    float* k; cudaGetSymbolAddress((void**)&k, g_k);
    float* v; cudaGetSymbolAddress((void**)&v, g_v);
    float* attn; cudaGetSymbolAddress((void**)&attn, g_attn);

    cudaFuncSetAttribute(gemm_h, cudaFuncAttributeMaxDynamicSharedMemorySize,
                         GEMM_H_SMEM);
    cudaFuncSetAttribute(gemm_h_qkv, cudaFuncAttributeMaxDynamicSharedMemorySize,
                         GEMM_H_SMEM);
    cudaFuncSetAttribute(attn_kernel, cudaFuncAttributeMaxDynamicSharedMemorySize,
                         ATTN_SMEM_BYTES);

    // RoPE table (cheap)
    rope_table_kernel<<<(SEQ * 64 + 255) / 256, 256>>>();

    // Fused QKV projection (fp16 wmma)
    gemm_h_qkv<<<dim3((NH * HD + 2 * NKV * HD) / 128, MTOK / 128), 512,
                 GEMM_H_SMEM>>>(x, wq, wk, wv, q, k, v);

    // RoPE on q and k
    {
        int totq = MTOK * NH * (HD / 2);
        int totk = MTOK * NKV * (HD / 2);
        rope_apply_kernel<<<(totq + 255) / 256, 256>>>(q, NH, totq);
        rope_apply_kernel<<<(totk + 255) / 256, 256>>>(k, NKV, totk);
    }

    // Flash attention
    attn_kernel<<<dim3(SEQ / 64, BATCH * NH), 256, ATTN_SMEM_BYTES>>>(q, k, v, attn);

    // Output projection (fp16 wmma)
    gemm_h<<<dim3(DIMSZ / 128, MTOK / 128), 512, GEMM_H_SMEM>>>(attn, wo, out, DIMSZ, DIMSZ);
}

// round 12
// speedup vs baseline: 3.3292x; 1.6763x over previous
// Round 12: fp16 WMMA flash attention (QK^T + PV on HMMA, fp32 softmax/accum)
// + fp16 WMMA GEMMs from R10. tcgen05 unavailable (harness targets sm_103, no 'a').
#include <cuda_runtime.h>
#include <cuda_fp16.h>
#include <mma.h>
#include <math.h>
#include <cstdint>

using namespace nvcuda;

#define BATCH 2
#define SEQ   2048
#define DIMSZ 4096
#define NH    32
#define NKV   8
#define HD    128
#define MTOK  (BATCH * SEQ)   // 4096 tokens

// ---------------- scratch (static device memory; no allocs allowed) ----------
__device__ float g_q[(size_t)MTOK * NH * HD];     // 67 MB
__device__ float g_k[(size_t)MTOK * NKV * HD];    // 16.8 MB
__device__ float g_v[(size_t)MTOK * NKV * HD];    // 16.8 MB
__device__ float g_attn[(size_t)MTOK * NH * HD];  // 67 MB
__device__ float g_ctab[SEQ * 64];                // rope cos table
__device__ float g_stab[SEQ * 64];                // rope sin table

// ---------------- fp16 WMMA GEMM (unchanged from R10, passing) ---------------
#define HA_LD 40
#define HB_LD 136
#define HSTAGE_A (128 * HA_LD)
#define HSTAGE_B (32 * HB_LD)
#define GEMM_H_SMEM ((2 * (HSTAGE_A + HSTAGE_B)) * 2)

__device__ __forceinline__ void gemm_h_core(
    const float* __restrict__ A, const float* __restrict__ B,
    float* __restrict__ C, int Ndim, int Kdim, int bm, int bn, __half* hsm)
{
    __half* AsBase = hsm;
    __half* BsBase = hsm + 2 * HSTAGE_A;

    const int tid  = threadIdx.x;
    const int warp = tid >> 5;
    const int wr = warp >> 2;
    const int wc = warp & 3;

    const int arow = tid >> 2;
    const int acol = (tid & 3) * 8;
    const int brow = tid >> 4;
    const int bcol = (tid & 15) * 8;

    wmma::fragment<wmma::accumulator, 16, 16, 16, float> acc[2][2];
#pragma unroll
    for (int i = 0; i < 2; i++)
#pragma unroll
        for (int j = 0; j < 2; j++)
            wmma::fill_fragment(acc[i][j], 0.0f);

    const int niter = Kdim >> 5;

    float4 a0, a1, b0, b1;
    auto ldg_chunk = [&](int k0) {
        const float* ap = &A[(size_t)(bm + arow) * Kdim + k0 + acol];
        a0 = *(const float4*)ap;
        a1 = *(const float4*)(ap + 4);
        const float* bp = &B[(size_t)(k0 + brow) * Ndim + bn + bcol];
        b0 = *(const float4*)bp;
        b1 = *(const float4*)(bp + 4);
    };
    auto sts_chunk = [&](int stage) {
        __half* As = AsBase + stage * HSTAGE_A;
        __half* Bs = BsBase + stage * HSTAGE_B;
        __half2 p[4];
        p[0] = __floats2half2_rn(a0.x, a0.y);
        p[1] = __floats2half2_rn(a0.z, a0.w);
        p[2] = __floats2half2_rn(a1.x, a1.y);
        p[3] = __floats2half2_rn(a1.z, a1.w);
        *(uint4*)&As[arow * HA_LD + acol] = *(uint4*)p;
        p[0] = __floats2half2_rn(b0.x, b0.y);
        p[1] = __floats2half2_rn(b0.z, b0.w);
        p[2] = __floats2half2_rn(b1.x, b1.y);
        p[3] = __floats2half2_rn(b1.z, b1.w);
        *(uint4*)&Bs[brow * HB_LD + bcol] = *(uint4*)p;
    };

    ldg_chunk(0);
    sts_chunk(0);
    __syncthreads();

    for (int it = 0; it < niter; it++) {
        const bool more = (it + 1 < niter);
        if (more) ldg_chunk((it + 1) << 5);

        const __half* As = AsBase + (it & 1) * HSTAGE_A;
        const __half* Bs = BsBase + (it & 1) * HSTAGE_B;

#pragma unroll
        for (int kk = 0; kk < 32; kk += 16) {
            wmma::fragment<wmma::matrix_a, 16, 16, 16, __half, wmma::row_major> af[2];
            wmma::fragment<wmma::matrix_b, 16, 16, 16, __half, wmma::row_major> bf[2];
#pragma unroll
            for (int i = 0; i < 2; i++)
                wmma::load_matrix_sync(af[i], &As[(wr * 32 + i * 16) * HA_LD + kk], HA_LD);
#pragma unroll
            for (int j = 0; j < 2; j++)
                wmma::load_matrix_sync(bf[j], &Bs[kk * HB_LD + wc * 32 + j * 16], HB_LD);
#pragma unroll
            for (int i = 0; i < 2; i++)
#pragma unroll
                for (int j = 0; j < 2; j++)
                    wmma::mma_sync(acc[i][j], af[i], bf[j], acc[i][j]);
        }

        if (more) sts_chunk((it + 1) & 1);
        __syncthreads();
    }

#pragma unroll
    for (int i = 0; i < 2; i++)
#pragma unroll
        for (int j = 0; j < 2; j++)
            wmma::store_matrix_sync(
                &C[(size_t)(bm + wr * 32 + i * 16) * Ndim + bn + wc * 32 + j * 16],
                acc[i][j], Ndim, wmma::mem_row_major);
}

__global__ __launch_bounds__(512, 1) void gemm_h(
    const float* __restrict__ A, const float* __restrict__ B,
    float* __restrict__ C, int Ndim, int Kdim)
{
    extern __shared__ __half hsm[];
    gemm_h_core(A, B, C, Ndim, Kdim, blockIdx.y * 128, blockIdx.x * 128, hsm);
}

__global__ __launch_bounds__(512, 1) void gemm_h_qkv(
    const float* __restrict__ x,
    const float* __restrict__ wq, const float* __restrict__ wk,
    const float* __restrict__ wv,
    float* __restrict__ q, float* __restrict__ k, float* __restrict__ v)
{
    extern __shared__ __half hsm[];
    const int bnTot = blockIdx.x * 128;
    const float* W;
    float* Out;
    int Nw, bn;
    if (bnTot < NH * HD)                 { W = wq; Out = q; Nw = NH * HD;  bn = bnTot; }
    else if (bnTot < NH * HD + NKV * HD) { W = wk; Out = k; Nw = NKV * HD; bn = bnTot - NH * HD; }
    else                                 { W = wv; Out = v; Nw = NKV * HD; bn = bnTot - NH * HD - NKV * HD; }
    gemm_h_core(x, W, Out, Nw, DIMSZ, blockIdx.y * 128, bn, hsm);
}

// ---------------- RoPE (unchanged) -------------------------------------------
__global__ void rope_table_kernel()
{
    int idx = blockIdx.x * blockDim.x + threadIdx.x;
    if (idx >= SEQ * 64) return;
    int pos = idx >> 6;
    int p = idx & 63;
    double inv = exp(((double)(-2 * p) / 128.0) * log(500000.0));
    float angf = (float)pos * (float)inv;
    double ar = fmod((double)angf, 6.283185307179586476925287);
    float fa = (float)ar;
    g_ctab[idx] = cosf(fa);
    g_stab[idx] = sinf(fa);
}

__global__ void rope_apply_kernel(float* __restrict__ t, int nheads, int total)
{
    int idx = blockIdx.x * blockDim.x + threadIdx.x;
    if (idx >= total) return;
    int p = idx & 63;
    int rest = idx >> 6;
    int tok = rest / nheads;
    int pos = tok & (SEQ - 1);

    float c = g_ctab[pos * 64 + p];
    float s = g_stab[pos * 64 + p];

    float2* base = (float2*)(t + (size_t)rest * HD + 2 * p);
    float2 ab = *base;
    float2 o;
    o.x = ab.x * c - ab.y * s;
    o.y = ab.x * s + ab.y * c;
    *base = o;
}

// ---------------- fp16 WMMA flash attention ----------------------------------
// grid (32 q-tiles, 64 batch*head), block 256 (8 warps: 4 in M x 2 in N).
// Tiles: Q/K/V 64x128 fp16; S/P 64x64; PV partial 64x128 fp32 scratch.
// Softmax stats and running O stay fp32; rescale in per-thread registers.
#define AT_LDH 136   // half stride for Q/K/V rows (128 + 8 pad)
#define AT_LDS 72    // S / P16 stride (64 + 8 pad)
#define AT_LDO 132   // PV fp32 stride (128 + 4 pad)
#define ATTN_H_SMEM (3 * 64 * AT_LDH * 2 + 64 * AT_LDS * 4 + 64 * AT_LDS * 2 \
                     + 64 * AT_LDO * 4 + 3 * 64 * 4)

__global__ __launch_bounds__(256, 1) void attn_h_kernel(
    const float* __restrict__ q, const float* __restrict__ k,
    const float* __restrict__ v, float* __restrict__ o)
{
    extern __shared__ char smraw[];
    __half* Qs  = (__half*)smraw;                    // 64 x AT_LDH
    __half* Ks  = Qs + 64 * AT_LDH;                  // 64 x AT_LDH
    __half* Vs  = Ks + 64 * AT_LDH;                  // 64 x AT_LDH
    float*  Ss  = (float*)(Vs + 64 * AT_LDH);        // 64 x AT_LDS (fp32)
    __half* P16 = (__half*)(Ss + 64 * AT_LDS);       // 64 x AT_LDS (fp16)
    float*  PVs = (float*)(P16 + 64 * AT_LDS);       // 64 x AT_LDO (fp32)
    float*  rowm = PVs + 64 * AT_LDO;
    float*  rowl = rowm + 64;
    float*  salpha = rowl + 64;

    const int tid = threadIdx.x;
    const int tx = tid & 15;
    const int ty = tid >> 4;
    const int warp = tid >> 5;
    const int wm = warp >> 1;    // 0..3 (M)
    const int wn = warp & 1;     // 0..1 (N)
    const int qtile = blockIdx.x;
    const int bh = blockIdx.y;
    const int b = bh / NH;
    const int h = bh % NH;
    const int kvh = h / (NH / NKV);
    const float scale = 0.08838834764831845f;  // 1/sqrt(128)

    // Load + convert Q tile (pre-scaled)
#pragma unroll
    for (int i = 0; i < 8; i++) {
        int fid = tid + i * 256;
        int r = fid >> 5;
        int c4 = (fid & 31) << 2;
        int sq = qtile * 64 + r;
        float4 vq = *(const float4*)&q[(((size_t)(b * SEQ + sq)) * NH + h) * HD + c4];
        __half2 h01 = __floats2half2_rn(vq.x * scale, vq.y * scale);
        __half2 h23 = __floats2half2_rn(vq.z * scale, vq.w * scale);
        uint2 pk = { *(unsigned*)&h01, *(unsigned*)&h23 };
        *(uint2*)&Qs[r * AT_LDH + c4] = pk;
    }
    if (tid < 64) { rowm[tid] = -INFINITY; rowl[tid] = 0.0f; }

    float Oacc[4][8];
#pragma unroll
    for (int i = 0; i < 4; i++)
#pragma unroll
        for (int cc = 0; cc < 8; cc++) Oacc[i][cc] = 0.0f;
    __syncthreads();

    for (int kt = 0; kt <= qtile; kt++) {
        // Load + convert K,V tiles
#pragma unroll
        for (int i = 0; i < 8; i++) {
            int fid = tid + i * 256;
            int r = fid >> 5;
            int c4 = (fid & 31) << 2;
            int sk = kt * 64 + r;
            size_t gidx = (((size_t)(b * SEQ + sk)) * NKV + kvh) * HD + c4;
            float4 kv4 = *(const float4*)&k[gidx];
            float4 vv4 = *(const float4*)&v[gidx];
            __half2 k01 = __floats2half2_rn(kv4.x, kv4.y);
            __half2 k23 = __floats2half2_rn(kv4.z, kv4.w);
            __half2 v01 = __floats2half2_rn(vv4.x, vv4.y);
            __half2 v23 = __floats2half2_rn(vv4.z, vv4.w);
            uint2 kk2 = { *(unsigned*)&k01, *(unsigned*)&k23 };
            uint2 vv2 = { *(unsigned*)&v01, *(unsigned*)&v23 };
            *(uint2*)&Ks[r * AT_LDH + c4] = kk2;
            *(uint2*)&Vs[r * AT_LDH + c4] = vv2;
        }
        __syncthreads();

        // S = Q @ K^T : warp computes 16x32 strip (2 n-tiles)
        {
            wmma::fragment<wmma::accumulator, 16, 16, 16, float> sfrag[2];
#pragma unroll
            for (int j = 0; j < 2; j++) wmma::fill_fragment(sfrag[j], 0.0f);
#pragma unroll
            for (int kk = 0; kk < 128; kk += 16) {
                wmma::fragment<wmma::matrix_a, 16, 16, 16, __half, wmma::row_major> aq;
                wmma::load_matrix_sync(aq, &Qs[(wm * 16) * AT_LDH + kk], AT_LDH);
#pragma unroll
                for (int j = 0; j < 2; j++) {
                    wmma::fragment<wmma::matrix_b, 16, 16, 16, __half, wmma::col_major> bk;
                    wmma::load_matrix_sync(bk, &Ks[(wn * 32 + j * 16) * AT_LDH + kk], AT_LDH);
                    wmma::mma_sync(sfrag[j], aq, bk, sfrag[j]);
                }
            }
#pragma unroll
            for (int j = 0; j < 2; j++)
                wmma::store_matrix_sync(&Ss[(wm * 16) * AT_LDS + wn * 32 + j * 16],
                                        sfrag[j], AT_LDS, wmma::mem_row_major);
        }
        __syncthreads();

        // Causal mask on the diagonal tile
        const bool diag = (kt == qtile);
        if (diag) {
            for (int idx2 = tid; idx2 < 4096; idx2 += 256) {
                int r = idx2 >> 6, c = idx2 & 63;
                if (c > r) Ss[r * AT_LDS + c] = -1e9f;
            }
            __syncthreads();
        }

        // Row max + alpha (fp32)
        if (tid < 64) {
            float mold = rowm[tid];
            float mx = mold;
            const float* sr = &Ss[tid * AT_LDS];
#pragma unroll 8
            for (int c = 0; c < 64; c++) mx = fmaxf(mx, sr[c]);
            rowm[tid] = mx;
            salpha[tid] = __expf(mold - mx);
        }
        __syncthreads();

        // Exponentiate: fp32 into Ss (for rowsum), fp16 into P16 (for MMA)
        for (int idx2 = tid; idx2 < 4096; idx2 += 256) {
            int r = idx2 >> 6, c = idx2 & 63;
            float p = __expf(Ss[r * AT_LDS + c] - rowm[r]);
            Ss[r * AT_LDS + c] = p;
            P16[r * AT_LDS + c] = __float2half_rn(p);
        }
        __syncthreads();

        // Row sums (fp32) — runs alongside PV MMA issue
        if (tid < 64) {
            float ssum = 0.0f;
            const float* sr = &Ss[tid * AT_LDS];
#pragma unroll 8
            for (int c = 0; c < 64; c++) ssum += sr[c];
            rowl[tid] = rowl[tid] * salpha[tid] + ssum;
        }

        // PV = P16 @ Vs : warp computes 16x64 strip (4 n-tiles)
        {
            wmma::fragment<wmma::accumulator, 16, 16, 16, float> ofrag[4];
#pragma unroll
            for (int j = 0; j < 4; j++) wmma::fill_fragment(ofrag[j], 0.0f);
#pragma unroll
            for (int cs = 0; cs < 64; cs += 16) {
                wmma::fragment<wmma::matrix_a, 16, 16, 16, __half, wmma::row_major> ap;
                wmma::load_matrix_sync(ap, &P16[(wm * 16) * AT_LDS + cs], AT_LDS);
#pragma unroll
                for (int j = 0; j < 4; j++) {
                    wmma::fragment<wmma::matrix_b, 16, 16, 16, __half, wmma::row_major> bv;
                    wmma::load_matrix_sync(bv, &Vs[cs * AT_LDH + wn * 64 + j * 16], AT_LDH);
                    wmma::mma_sync(ofrag[j], ap, bv, ofrag[j]);
                }
            }
#pragma unroll
            for (int j = 0; j < 4; j++)
                wmma::store_matrix_sync(&PVs[(wm * 16) * AT_LDO + wn * 64 + j * 16],
                                        ofrag[j], AT_LDO, wmma::mem_row_major);
        }
        __syncthreads();

        // Running O update in registers: O = O*alpha + PV
#pragma unroll
        for (int i = 0; i < 4; i++) {
            int r = ty + 16 * i;
            float a = salpha[r];
            const float* pv = &PVs[r * AT_LDO + tx * 8];
#pragma unroll
            for (int cc = 0; cc < 8; cc++)
                Oacc[i][cc] = Oacc[i][cc] * a + pv[cc];
        }
        __syncthreads();
    }

    // Normalize + write
#pragma unroll
    for (int i = 0; i < 4; i++) {
        int r = ty + 16 * i;
        int sq = qtile * 64 + r;
        float invl = 1.0f / rowl[r];
        float4 o0, o1;
        o0.x = Oacc[i][0] * invl; o0.y = Oacc[i][1] * invl;
        o0.z = Oacc[i][2] * invl; o0.w = Oacc[i][3] * invl;
        o1.x = Oacc[i][4] * invl; o1.y = Oacc[i][5] * invl;
        o1.z = Oacc[i][6] * invl; o1.w = Oacc[i][7] * invl;
        float* op = &o[(((size_t)(b * SEQ + sq)) * NH + h) * HD + tx * 8];
        *(float4*)&op[0] = o0;
        *(float4*)&op[4] = o1;
    }
}

// ---------------- launch ------------------------------------------------------
extern "C" void kernel_launch(void* const* d_in, const int* in_sizes, int n_in,
                              void* d_out, int out_size)
{
    const float* x  = (const float*)d_in[0];
    const float* wq = (const float*)d_in[1];
    const float* wk = (const float*)d_in[2];
    const float* wv = (const float*)d_in[3];
    const float* wo = (const float*)d_in[4];
    float* out = (float*)d_out;

    float* q; cudaGetSymbolAddress((void**)&q, g_q);
    float* k; cudaGetSymbolAddress((void**)&k, g_k);
    float* v; cudaGetSymbolAddress((void**)&v, g_v);
    float* attn; cudaGetSymbolAddress((void**)&attn, g_attn);

    cudaFuncSetAttribute(gemm_h, cudaFuncAttributeMaxDynamicSharedMemorySize,
                         GEMM_H_SMEM);
    cudaFuncSetAttribute(gemm_h_qkv, cudaFuncAttributeMaxDynamicSharedMemorySize,
                         GEMM_H_SMEM);
    cudaFuncSetAttribute(attn_h_kernel, cudaFuncAttributeMaxDynamicSharedMemorySize,
                         ATTN_H_SMEM);

    // RoPE table (cheap)
    rope_table_kernel<<<(SEQ * 64 + 255) / 256, 256>>>();

    // Fused QKV projection (fp16 wmma)
    gemm_h_qkv<<<dim3((NH * HD + 2 * NKV * HD) / 128, MTOK / 128), 512,
                 GEMM_H_SMEM>>>(x, wq, wk, wv, q, k, v);

    // RoPE on q and k
    {
        int totq = MTOK * NH * (HD / 2);
        int totk = MTOK * NKV * (HD / 2);
        rope_apply_kernel<<<(totq + 255) / 256, 256>>>(q, NH, totq);
        rope_apply_kernel<<<(totk + 255) / 256, 256>>>(k, NKV, totk);
    }

    // Flash attention (fp16 wmma)
    attn_h_kernel<<<dim3(SEQ / 64, BATCH * NH), 256, ATTN_H_SMEM>>>(q, k, v, attn);

    // Output projection (fp16 wmma)
    gemm_h<<<dim3(DIMSZ / 128, MTOK / 128), 512, GEMM_H_SMEM>>>(attn, wo, out, DIMSZ, DIMSZ);
}

// round 14
// speedup vs baseline: 4.7533x; 1.4278x over previous
// Round 13: end-to-end fp16 GEMM datapath (pre-converted operands, cp.async
// 3-stage pipeline, no in-loop CVT) + fp16 WMMA flash attention (fp16 output).
#include <cuda_runtime.h>
#include <cuda_fp16.h>
#include <mma.h>
#include <math.h>
#include <cstdint>

using namespace nvcuda;

#define BATCH 2
#define SEQ   2048
#define DIMSZ 4096
#define NH    32
#define NKV   8
#define HD    128
#define MTOK  (BATCH * SEQ)   // 4096 tokens

// ---------------- scratch (static device memory; no allocs allowed) ----------
__device__ float  g_q[(size_t)MTOK * NH * HD];      // 67 MB fp32 (rope reads)
__device__ float  g_k[(size_t)MTOK * NKV * HD];     // 16.8 MB
__device__ float  g_v[(size_t)MTOK * NKV * HD];     // 16.8 MB
__device__ __half g_attn_h[(size_t)MTOK * NH * HD]; // 33.5 MB fp16
__device__ __half g_xh[(size_t)MTOK * DIMSZ];       // 33.5 MB
__device__ __half g_wqh[(size_t)DIMSZ * NH * HD];   // 33.5 MB
__device__ __half g_wkh[(size_t)DIMSZ * NKV * HD];  // 8.4 MB
__device__ __half g_wvh[(size_t)DIMSZ * NKV * HD];  // 8.4 MB
__device__ __half g_woh[(size_t)NH * HD * DIMSZ];   // 33.5 MB
__device__ float  g_ctab[SEQ * 64];
__device__ float  g_stab[SEQ * 64];

// ---------------- fp32 -> fp16 conversion (vectorized) -----------------------
__global__ void f2h_kernel(const float* __restrict__ in, __half* __restrict__ out,
                           int n4)
{
    int i = blockIdx.x * blockDim.x + threadIdx.x;
    if (i >= n4) return;
    float4 v = ((const float4*)in)[i];
    __half2 a = __floats2half2_rn(v.x, v.y);
    __half2 b = __floats2half2_rn(v.z, v.w);
    uint2 p = { *(unsigned*)&a, *(unsigned*)&b };
    ((uint2*)out)[i] = p;
}

// ---------------- cp.async helpers -------------------------------------------
__device__ __forceinline__ void cp_async16h(__half* dst, const __half* src) {
    unsigned s = (unsigned)__cvta_generic_to_shared(dst);
    asm volatile("cp.async.cg.shared.global [%0], [%1], 16;\n" :: "r"(s), "l"(src));
}

// ---------------- fp16-in GEMM: C[M,N](fp32) = A[M,K](h) @ B[K,N](h) ---------
// Block 128x128, 256 threads (8 warps, 4Mx2N), warp tile 32x64, K-step 32.
// 3-stage cp.async pipeline; fp16 flows gmem->smem untouched.
#define GA_LD 40                          // A row stride (32 + 8 pad) halfs
#define GB_LD 136                         // B row stride (128 + 8 pad) halfs
#define GSTG  (128 * GA_LD + 32 * GB_LD)  // halfs per stage: 9472
#define GEMM_H_SMEM (3 * GSTG * 2)        // 56832 B

__device__ __forceinline__ void gemm_h_core(
    const __half* __restrict__ A, const __half* __restrict__ B,
    float* __restrict__ C, int Ndim, int Kdim, int bm, int bn, __half* hsm)
{
    const int tid  = threadIdx.x;
    const int warp = tid >> 5;
    const int wr = warp >> 1;    // 0..3 (M)
    const int wc = warp & 1;     // 0..1 (N)

    // A: 128x32 halfs = 512 x 16B chunks; thread does rows ar, ar+64
    const int ar = tid >> 2;
    const int ac = (tid & 3) * 8;
    // B: 32x128 halfs = 512 chunks; thread does rows br, br+16
    const int br = tid >> 4;
    const int bc = (tid & 15) * 8;

    auto issue = [&](int it) {
        const int k0 = it << 5;
        __half* As = hsm + (it % 3) * GSTG;
        __half* Bs = As + 128 * GA_LD;
        cp_async16h(&As[ar * GA_LD + ac],        &A[(size_t)(bm + ar) * Kdim + k0 + ac]);
        cp_async16h(&As[(ar + 64) * GA_LD + ac], &A[(size_t)(bm + ar + 64) * Kdim + k0 + ac]);
        cp_async16h(&Bs[br * GB_LD + bc],        &B[(size_t)(k0 + br) * Ndim + bn + bc]);
        cp_async16h(&Bs[(br + 16) * GB_LD + bc], &B[(size_t)(k0 + br + 16) * Ndim + bn + bc]);
        asm volatile("cp.async.commit_group;\n" ::: "memory");
    };

    wmma::fragment<wmma::accumulator, 16, 16, 16, float> acc[2][4];
#pragma unroll
    for (int i = 0; i < 2; i++)
#pragma unroll
        for (int j = 0; j < 4; j++)
            wmma::fill_fragment(acc[i][j], 0.0f);

    const int niter = Kdim >> 5;
    issue(0);
    issue(1);

    for (int it = 0; it < niter; it++) {
        if (it + 2 < niter) {
            issue(it + 2);
            asm volatile("cp.async.wait_group 2;\n" ::: "memory");
        } else if (it + 1 < niter) {
            asm volatile("cp.async.wait_group 1;\n" ::: "memory");
        } else {
            asm volatile("cp.async.wait_group 0;\n" ::: "memory");
        }
        __syncthreads();

        const __half* As = hsm + (it % 3) * GSTG;
        const __half* Bs = As + 128 * GA_LD;

#pragma unroll
        for (int kk = 0; kk < 32; kk += 16) {
            wmma::fragment<wmma::matrix_a, 16, 16, 16, __half, wmma::row_major> af[2];
            wmma::fragment<wmma::matrix_b, 16, 16, 16, __half, wmma::row_major> bf[4];
#pragma unroll
            for (int i = 0; i < 2; i++)
                wmma::load_matrix_sync(af[i], &As[(wr * 32 + i * 16) * GA_LD + kk], GA_LD);
#pragma unroll
            for (int j = 0; j < 4; j++)
                wmma::load_matrix_sync(bf[j], &Bs[kk * GB_LD + wc * 64 + j * 16], GB_LD);
#pragma unroll
            for (int i = 0; i < 2; i++)
#pragma unroll
                for (int j = 0; j < 4; j++)
                    wmma::mma_sync(acc[i][j], af[i], bf[j], acc[i][j]);
        }
        __syncthreads();   // done reading this stage before it is overwritten
    }

#pragma unroll
    for (int i = 0; i < 2; i++)
#pragma unroll
        for (int j = 0; j < 4; j++)
            wmma::store_matrix_sync(
                &C[(size_t)(bm + wr * 32 + i * 16) * Ndim + bn + wc * 64 + j * 16],
                acc[i][j], Ndim, wmma::mem_row_major);
}

__global__ __launch_bounds__(256, 2) void gemm_h(
    const __half* __restrict__ A, const __half* __restrict__ B,
    float* __restrict__ C, int Ndim, int Kdim)
{
    extern __shared__ __half hsm[];
    gemm_h_core(A, B, C, Ndim, Kdim, blockIdx.y * 128, blockIdx.x * 128, hsm);
}

__global__ __launch_bounds__(256, 2) void gemm_h_qkv(
    const __half* __restrict__ xh,
    const __half* __restrict__ wqh, const __half* __restrict__ wkh,
    const __half* __restrict__ wvh,
    float* __restrict__ q, float* __restrict__ k, float* __restrict__ v)
{
    extern __shared__ __half hsm[];
    const int bnTot = blockIdx.x * 128;
    const __half* W;
    float* Out;
    int Nw, bn;
    if (bnTot < NH * HD)                 { W = wqh; Out = q; Nw = NH * HD;  bn = bnTot; }
    else if (bnTot < NH * HD + NKV * HD) { W = wkh; Out = k; Nw = NKV * HD; bn = bnTot - NH * HD; }
    else                                 { W = wvh; Out = v; Nw = NKV * HD; bn = bnTot - NH * HD - NKV * HD; }
    gemm_h_core(xh, W, Out, Nw, DIMSZ, blockIdx.y * 128, bn, hsm);
}

// ---------------- RoPE (unchanged) -------------------------------------------
__global__ void rope_table_kernel()
{
    int idx = blockIdx.x * blockDim.x + threadIdx.x;
    if (idx >= SEQ * 64) return;
    int pos = idx >> 6;
    int p = idx & 63;
    double inv = exp(((double)(-2 * p) / 128.0) * log(500000.0));
    float angf = (float)pos * (float)inv;
    double ar = fmod((double)angf, 6.283185307179586476925287);
    float fa = (float)ar;
    g_ctab[idx] = cosf(fa);
    g_stab[idx] = sinf(fa);
}

__global__ void rope_apply_kernel(float* __restrict__ t, int nheads, int total)
{
    int idx = blockIdx.x * blockDim.x + threadIdx.x;
    if (idx >= total) return;
    int p = idx & 63;
    int rest = idx >> 6;
    int tok = rest / nheads;
    int pos = tok & (SEQ - 1);

    float c = g_ctab[pos * 64 + p];
    float s = g_stab[pos * 64 + p];

    float2* base = (float2*)(t + (size_t)rest * HD + 2 * p);
    float2 ab = *base;
    float2 o;
    o.x = ab.x * c - ab.y * s;
    o.y = ab.x * s + ab.y * c;
    *base = o;
}

// ---------------- fp16 WMMA flash attention (output now fp16) ----------------
#define AT_LDH 136
#define AT_LDS 72
#define AT_LDO 132
#define ATTN_H_SMEM (3 * 64 * AT_LDH * 2 + 64 * AT_LDS * 4 + 64 * AT_LDS * 2 \
                     + 64 * AT_LDO * 4 + 3 * 64 * 4)

__global__ __launch_bounds__(256, 1) void attn_h_kernel(
    const float* __restrict__ q, const float* __restrict__ k,
    const float* __restrict__ v, __half* __restrict__ o)
{
    extern __shared__ char smraw[];
    __half* Qs  = (__half*)smraw;
    __half* Ks  = Qs + 64 * AT_LDH;
    __half* Vs  = Ks + 64 * AT_LDH;
    float*  Ss  = (float*)(Vs + 64 * AT_LDH);
    __half* P16 = (__half*)(Ss + 64 * AT_LDS);
    float*  PVs = (float*)(P16 + 64 * AT_LDS);
    float*  rowm = PVs + 64 * AT_LDO;
    float*  rowl = rowm + 64;
    float*  salpha = rowl + 64;

    const int tid = threadIdx.x;
    const int tx = tid & 15;
    const int ty = tid >> 4;
    const int warp = tid >> 5;
    const int wm = warp >> 1;
    const int wn = warp & 1;
    const int qtile = blockIdx.x;
    const int bh = blockIdx.y;
    const int b = bh / NH;
    const int h = bh % NH;
    const int kvh = h / (NH / NKV);
    const float scale = 0.08838834764831845f;

#pragma unroll
    for (int i = 0; i < 8; i++) {
        int fid = tid + i * 256;
        int r = fid >> 5;
        int c4 = (fid & 31) << 2;
        int sq = qtile * 64 + r;
        float4 vq = *(const float4*)&q[(((size_t)(b * SEQ + sq)) * NH + h) * HD + c4];
        __half2 h01 = __floats2half2_rn(vq.x * scale, vq.y * scale);
        __half2 h23 = __floats2half2_rn(vq.z * scale, vq.w * scale);
        uint2 pk = { *(unsigned*)&h01, *(unsigned*)&h23 };
        *(uint2*)&Qs[r * AT_LDH + c4] = pk;
    }
    if (tid < 64) { rowm[tid] = -INFINITY; rowl[tid] = 0.0f; }

    float Oacc[4][8];
#pragma unroll
    for (int i = 0; i < 4; i++)
#pragma unroll
        for (int cc = 0; cc < 8; cc++) Oacc[i][cc] = 0.0f;
    __syncthreads();

    for (int kt = 0; kt <= qtile; kt++) {
#pragma unroll
        for (int i = 0; i < 8; i++) {
            int fid = tid + i * 256;
            int r = fid >> 5;
            int c4 = (fid & 31) << 2;
            int sk = kt * 64 + r;
            size_t gidx = (((size_t)(b * SEQ + sk)) * NKV + kvh) * HD + c4;
            float4 kv4 = *(const float4*)&k[gidx];
            float4 vv4 = *(const float4*)&v[gidx];
            __half2 k01 = __floats2half2_rn(kv4.x, kv4.y);
            __half2 k23 = __floats2half2_rn(kv4.z, kv4.w);
            __half2 v01 = __floats2half2_rn(vv4.x, vv4.y);
            __half2 v23 = __floats2half2_rn(vv4.z, vv4.w);
            uint2 kk2 = { *(unsigned*)&k01, *(unsigned*)&k23 };
            uint2 vv2 = { *(unsigned*)&v01, *(unsigned*)&v23 };
            *(uint2*)&Ks[r * AT_LDH + c4] = kk2;
            *(uint2*)&Vs[r * AT_LDH + c4] = vv2;
        }
        __syncthreads();

        {
            wmma::fragment<wmma::accumulator, 16, 16, 16, float> sfrag[2];
#pragma unroll
            for (int j = 0; j < 2; j++) wmma::fill_fragment(sfrag[j], 0.0f);
#pragma unroll
            for (int kk = 0; kk < 128; kk += 16) {
                wmma::fragment<wmma::matrix_a, 16, 16, 16, __half, wmma::row_major> aq;
                wmma::load_matrix_sync(aq, &Qs[(wm * 16) * AT_LDH + kk], AT_LDH);
#pragma unroll
                for (int j = 0; j < 2; j++) {
                    wmma::fragment<wmma::matrix_b, 16, 16, 16, __half, wmma::col_major> bk;
                    wmma::load_matrix_sync(bk, &Ks[(wn * 32 + j * 16) * AT_LDH + kk], AT_LDH);
                    wmma::mma_sync(sfrag[j], aq, bk, sfrag[j]);
                }
            }
#pragma unroll
            for (int j = 0; j < 2; j++)
                wmma::store_matrix_sync(&Ss[(wm * 16) * AT_LDS + wn * 32 + j * 16],
                                        sfrag[j], AT_LDS, wmma::mem_row_major);
        }
        __syncthreads();

        const bool diag = (kt == qtile);
        if (diag) {
            for (int idx2 = tid; idx2 < 4096; idx2 += 256) {
                int r = idx2 >> 6, c = idx2 & 63;
                if (c > r) Ss[r * AT_LDS + c] = -1e9f;
            }
            __syncthreads();
        }

        if (tid < 64) {
            float mold = rowm[tid];
            float mx = mold;
            const float* sr = &Ss[tid * AT_LDS];
#pragma unroll 8
            for (int c = 0; c < 64; c++) mx = fmaxf(mx, sr[c]);
            rowm[tid] = mx;
            salpha[tid] = __expf(mold - mx);
        }
        __syncthreads();

        for (int idx2 = tid; idx2 < 4096; idx2 += 256) {
            int r = idx2 >> 6, c = idx2 & 63;
            float p = __expf(Ss[r * AT_LDS + c] - rowm[r]);
            Ss[r * AT_LDS + c] = p;
            P16[r * AT_LDS + c] = __float2half_rn(p);
        }
        __syncthreads();

        if (tid < 64) {
            float ssum = 0.0f;
            const float* sr = &Ss[tid * AT_LDS];
#pragma unroll 8
            for (int c = 0; c < 64; c++) ssum += sr[c];
            rowl[tid] = rowl[tid] * salpha[tid] + ssum;
        }

        {
            wmma::fragment<wmma::accumulator, 16, 16, 16, float> ofrag[4];
#pragma unroll
            for (int j = 0; j < 4; j++) wmma::fill_fragment(ofrag[j], 0.0f);
#pragma unroll
            for (int cs = 0; cs < 64; cs += 16) {
                wmma::fragment<wmma::matrix_a, 16, 16, 16, __half, wmma::row_major> ap;
                wmma::load_matrix_sync(ap, &P16[(wm * 16) * AT_LDS + cs], AT_LDS);
#pragma unroll
                for (int j = 0; j < 4; j++) {
                    wmma::fragment<wmma::matrix_b, 16, 16, 16, __half, wmma::row_major> bv;
                    wmma::load_matrix_sync(bv, &Vs[cs * AT_LDH + wn * 64 + j * 16], AT_LDH);
                    wmma::mma_sync(ofrag[j], ap, bv, ofrag[j]);
                }
            }
#pragma unroll
            for (int j = 0; j < 4; j++)
                wmma::store_matrix_sync(&PVs[(wm * 16) * AT_LDO + wn * 64 + j * 16],
                                        ofrag[j], AT_LDO, wmma::mem_row_major);
        }
        __syncthreads();

#pragma unroll
        for (int i = 0; i < 4; i++) {
            int r = ty + 16 * i;
            float a = salpha[r];
            const float* pv = &PVs[r * AT_LDO + tx * 8];
#pragma unroll
            for (int cc = 0; cc < 8; cc++)
                Oacc[i][cc] = Oacc[i][cc] * a + pv[cc];
        }
        __syncthreads();
    }

    // Normalize + write as fp16 (same rounding the downstream GEMM applied before)
#pragma unroll
    for (int i = 0; i < 4; i++) {
        int r = ty + 16 * i;
        int sq = qtile * 64 + r;
        float invl = 1.0f / rowl[r];
        __half2 p0 = __floats2half2_rn(Oacc[i][0] * invl, Oacc[i][1] * invl);
        __half2 p1 = __floats2half2_rn(Oacc[i][2] * invl, Oacc[i][3] * invl);
        __half2 p2 = __floats2half2_rn(Oacc[i][4] * invl, Oacc[i][5] * invl);
        __half2 p3 = __floats2half2_rn(Oacc[i][6] * invl, Oacc[i][7] * invl);
        uint4 pk = { *(unsigned*)&p0, *(unsigned*)&p1, *(unsigned*)&p2, *(unsigned*)&p3 };
        *(uint4*)&o[(((size_t)(b * SEQ + sq)) * NH + h) * HD + tx * 8] = pk;
    }
}

// ---------------- launch ------------------------------------------------------
extern "C" void kernel_launch(void* const* d_in, const int* in_sizes, int n_in,
                              void* d_out, int out_size)
{
    const float* x  = (const float*)d_in[0];
    const float* wq = (const float*)d_in[1];
    const float* wk = (const float*)d_in[2];
    const float* wv = (const float*)d_in[3];
    const float* wo = (const float*)d_in[4];
    float* out = (float*)d_out;

    float*  q;  cudaGetSymbolAddress((void**)&q,  g_q);
    float*  k;  cudaGetSymbolAddress((void**)&k,  g_k);
    float*  v;  cudaGetSymbolAddress((void**)&v,  g_v);
    __half* ah; cudaGetSymbolAddress((void**)&ah, g_attn_h);
    __half* xh; cudaGetSymbolAddress((void**)&xh, g_xh);
    __half* wqh; cudaGetSymbolAddress((void**)&wqh, g_wqh);
    __half* wkh; cudaGetSymbolAddress((void**)&wkh, g_wkh);
    __half* wvh; cudaGetSymbolAddress((void**)&wvh, g_wvh);
    __half* woh; cudaGetSymbolAddress((void**)&woh, g_woh);

    cudaFuncSetAttribute(gemm_h, cudaFuncAttributeMaxDynamicSharedMemorySize,
                         GEMM_H_SMEM);
    cudaFuncSetAttribute(gemm_h_qkv, cudaFuncAttributeMaxDynamicSharedMemorySize,
                         GEMM_H_SMEM);
    cudaFuncSetAttribute(attn_h_kernel, cudaFuncAttributeMaxDynamicSharedMemorySize,
                         ATTN_H_SMEM);

    // fp32 -> fp16 operand conversion (rounding identical to previous in-GEMM CVT)
    {
        int n4x = MTOK * DIMSZ / 4;
        int n4q = DIMSZ * NH * HD / 4;
        int n4k = DIMSZ * NKV * HD / 4;
        f2h_kernel<<<(n4x + 255) / 256, 256>>>(x,  xh,  n4x);
        f2h_kernel<<<(n4q + 255) / 256, 256>>>(wq, wqh, n4q);
        f2h_kernel<<<(n4k + 255) / 256, 256>>>(wk, wkh, n4k);
        f2h_kernel<<<(n4k + 255) / 256, 256>>>(wv, wvh, n4k);
        f2h_kernel<<<(n4q + 255) / 256, 256>>>(wo, woh, n4q);
    }

    // RoPE table
    rope_table_kernel<<<(SEQ * 64 + 255) / 256, 256>>>();

    // Fused QKV projection (fp16 in, fp32 out)
    gemm_h_qkv<<<dim3((NH * HD + 2 * NKV * HD) / 128, MTOK / 128), 256,
                 GEMM_H_SMEM>>>(xh, wqh, wkh, wvh, q, k, v);

    // RoPE on q and k (fp32)
    {
        int totq = MTOK * NH * (HD / 2);
        int totk = MTOK * NKV * (HD / 2);
        rope_apply_kernel<<<(totq + 255) / 256, 256>>>(q, NH, totq);
        rope_apply_kernel<<<(totk + 255) / 256, 256>>>(k, NKV, totk);
    }

    // Flash attention (fp16 wmma, fp16 output)
    attn_h_kernel<<<dim3(SEQ / 64, BATCH * NH), 256, ATTN_H_SMEM>>>(q, k, v, ah);

    // Output projection (fp16 in, fp32 out)
    gemm_h<<<dim3(DIMSZ / 128, MTOK / 128), 256, GEMM_H_SMEM>>>(ah, woh, out, DIMSZ, DIMSZ);
}

// round 15
// speedup vs baseline: 4.8232x; 1.0147x over previous
// Round 15: 4-stage single-sync cp.async GEMM pipeline + MLP-4 f2h conversion.
// Numerics identical to R13 (rel_err must stay 0.0008529849).
#include <cuda_runtime.h>
#include <cuda_fp16.h>
#include <mma.h>
#include <math.h>
#include <cstdint>

using namespace nvcuda;

#define BATCH 2
#define SEQ   2048
#define DIMSZ 4096
#define NH    32
#define NKV   8
#define HD    128
#define MTOK  (BATCH * SEQ)   // 4096 tokens

// ---------------- scratch (static device memory; no allocs allowed) ----------
__device__ float  g_q[(size_t)MTOK * NH * HD];
__device__ float  g_k[(size_t)MTOK * NKV * HD];
__device__ float  g_v[(size_t)MTOK * NKV * HD];
__device__ __half g_attn_h[(size_t)MTOK * NH * HD];
__device__ __half g_xh[(size_t)MTOK * DIMSZ];
__device__ __half g_wqh[(size_t)DIMSZ * NH * HD];
__device__ __half g_wkh[(size_t)DIMSZ * NKV * HD];
__device__ __half g_wvh[(size_t)DIMSZ * NKV * HD];
__device__ __half g_woh[(size_t)NH * HD * DIMSZ];
__device__ float  g_ctab[SEQ * 64];
__device__ float  g_stab[SEQ * 64];

// ---------------- fp32 -> fp16 conversion, MLP=4 -----------------------------
__global__ void f2h_kernel(const float* __restrict__ in, __half* __restrict__ out,
                           int n4)
{
    int i = blockIdx.x * blockDim.x + threadIdx.x;
    const int stride = gridDim.x * blockDim.x;
    float4 v0, v1, v2, v3;
    int i1 = i + stride, i2 = i + 2 * stride, i3 = i + 3 * stride;
    bool p0 = i < n4, p1 = i1 < n4, p2 = i2 < n4, p3 = i3 < n4;
    if (p0) v0 = ((const float4*)in)[i];
    if (p1) v1 = ((const float4*)in)[i1];
    if (p2) v2 = ((const float4*)in)[i2];
    if (p3) v3 = ((const float4*)in)[i3];
    uint2 o0, o1, o2, o3;
    {
        __half2 a = __floats2half2_rn(v0.x, v0.y), b = __floats2half2_rn(v0.z, v0.w);
        o0.x = *(unsigned*)&a; o0.y = *(unsigned*)&b;
        a = __floats2half2_rn(v1.x, v1.y); b = __floats2half2_rn(v1.z, v1.w);
        o1.x = *(unsigned*)&a; o1.y = *(unsigned*)&b;
        a = __floats2half2_rn(v2.x, v2.y); b = __floats2half2_rn(v2.z, v2.w);
        o2.x = *(unsigned*)&a; o2.y = *(unsigned*)&b;
        a = __floats2half2_rn(v3.x, v3.y); b = __floats2half2_rn(v3.z, v3.w);
        o3.x = *(unsigned*)&a; o3.y = *(unsigned*)&b;
    }
    if (p0) ((uint2*)out)[i]  = o0;
    if (p1) ((uint2*)out)[i1] = o1;
    if (p2) ((uint2*)out)[i2] = o2;
    if (p3) ((uint2*)out)[i3] = o3;
}

// ---------------- cp.async helpers -------------------------------------------
__device__ __forceinline__ void cp_async16h(__half* dst, const __half* src) {
    unsigned s = (unsigned)__cvta_generic_to_shared(dst);
    asm volatile("cp.async.cg.shared.global [%0], [%1], 16;\n" :: "r"(s), "l"(src));
}

// ---------------- fp16-in GEMM: C[M,N](fp32) = A[M,K](h) @ B[K,N](h) ---------
// Block 128x128, 256 threads (8 warps, 4Mx2N), warp tile 32x64, K-step 32.
// 4-stage cp.async pipeline, ONE __syncthreads per iter:
//   wait(stage it); sync; issue(it+3)  [writes stage (it-1)%4, safe post-sync];
//   compute(stage it%4).
#define GA_LD 40
#define GB_LD 136
#define GSTG  (128 * GA_LD + 32 * GB_LD)     // 9472 halfs / stage
#define GEMM_H_SMEM (4 * GSTG * 2)           // 75776 B

__device__ __forceinline__ void gemm_h_core(
    const __half* __restrict__ A, const __half* __restrict__ B,
    float* __restrict__ C, int Ndim, int Kdim, int bm, int bn, __half* hsm)
{
    const int tid  = threadIdx.x;
    const int warp = tid >> 5;
    const int wr = warp >> 1;
    const int wc = warp & 1;

    const int ar = tid >> 2;
    const int ac = (tid & 3) * 8;
    const int br = tid >> 4;
    const int bc = (tid & 15) * 8;

    auto issue = [&](int it) {
        const int k0 = it << 5;
        __half* As = hsm + (it & 3) * GSTG;
        __half* Bs = As + 128 * GA_LD;
        cp_async16h(&As[ar * GA_LD + ac],        &A[(size_t)(bm + ar) * Kdim + k0 + ac]);
        cp_async16h(&As[(ar + 64) * GA_LD + ac], &A[(size_t)(bm + ar + 64) * Kdim + k0 + ac]);
        cp_async16h(&Bs[br * GB_LD + bc],        &B[(size_t)(k0 + br) * Ndim + bn + bc]);
        cp_async16h(&Bs[(br + 16) * GB_LD + bc], &B[(size_t)(k0 + br + 16) * Ndim + bn + bc]);
        asm volatile("cp.async.commit_group;\n" ::: "memory");
    };

    wmma::fragment<wmma::accumulator, 16, 16, 16, float> acc[2][4];
#pragma unroll
    for (int i = 0; i < 2; i++)
#pragma unroll
        for (int j = 0; j < 4; j++)
            wmma::fill_fragment(acc[i][j], 0.0f);

    const int niter = Kdim >> 5;
    issue(0);
    issue(1);
    issue(2);

    for (int it = 0; it < niter; it++) {
        // wait until group `it` has landed (allow up to 2 newer pending)
        if (it + 2 < niter) {
            asm volatile("cp.async.wait_group 2;\n" ::: "memory");
        } else if (it + 1 < niter) {
            asm volatile("cp.async.wait_group 1;\n" ::: "memory");
        } else {
            asm volatile("cp.async.wait_group 0;\n" ::: "memory");
        }
        __syncthreads();

        if (it + 3 < niter) issue(it + 3);   // stage (it-1)%4: all warps past sync

        const __half* As = hsm + (it & 3) * GSTG;
        const __half* Bs = As + 128 * GA_LD;

#pragma unroll
        for (int kk = 0; kk < 32; kk += 16) {
            wmma::fragment<wmma::matrix_a, 16, 16, 16, __half, wmma::row_major> af[2];
            wmma::fragment<wmma::matrix_b, 16, 16, 16, __half, wmma::row_major> bf[4];
#pragma unroll
            for (int i = 0; i < 2; i++)
                wmma::load_matrix_sync(af[i], &As[(wr * 32 + i * 16) * GA_LD + kk], GA_LD);
#pragma unroll
            for (int j = 0; j < 4; j++)
                wmma::load_matrix_sync(bf[j], &Bs[kk * GB_LD + wc * 64 + j * 16], GB_LD);
#pragma unroll
            for (int i = 0; i < 2; i++)
#pragma unroll
                for (int j = 0; j < 4; j++)
                    wmma::mma_sync(acc[i][j], af[i], bf[j], acc[i][j]);
        }
    }

#pragma unroll
    for (int i = 0; i < 2; i++)
#pragma unroll
        for (int j = 0; j < 4; j++)
            wmma::store_matrix_sync(
                &C[(size_t)(bm + wr * 32 + i * 16) * Ndim + bn + wc * 64 + j * 16],
                acc[i][j], Ndim, wmma::mem_row_major);
}

__global__ __launch_bounds__(256, 2) void gemm_h(
    const __half* __restrict__ A, const __half* __restrict__ B,
    float* __restrict__ C, int Ndim, int Kdim)
{
    extern __shared__ __half hsm[];
    gemm_h_core(A, B, C, Ndim, Kdim, blockIdx.y * 128, blockIdx.x * 128, hsm);
}

__global__ __launch_bounds__(256, 2) void gemm_h_qkv(
    const __half* __restrict__ xh,
    const __half* __restrict__ wqh, const __half* __restrict__ wkh,
    const __half* __restrict__ wvh,
    float* __restrict__ q, float* __restrict__ k, float* __restrict__ v)
{
    extern __shared__ __half hsm[];
    const int bnTot = blockIdx.x * 128;
    const __half* W;
    float* Out;
    int Nw, bn;
    if (bnTot < NH * HD)                 { W = wqh; Out = q; Nw = NH * HD;  bn = bnTot; }
    else if (bnTot < NH * HD + NKV * HD) { W = wkh; Out = k; Nw = NKV * HD; bn = bnTot - NH * HD; }
    else                                 { W = wvh; Out = v; Nw = NKV * HD; bn = bnTot - NH * HD - NKV * HD; }
    gemm_h_core(xh, W, Out, Nw, DIMSZ, blockIdx.y * 128, bn, hsm);
}

// ---------------- RoPE (unchanged) -------------------------------------------
__global__ void rope_table_kernel()
{
    int idx = blockIdx.x * blockDim.x + threadIdx.x;
    if (idx >= SEQ * 64) return;
    int pos = idx >> 6;
    int p = idx & 63;
    double inv = exp(((double)(-2 * p) / 128.0) * log(500000.0));
    float angf = (float)pos * (float)inv;
    double ar = fmod((double)angf, 6.283185307179586476925287);
    float fa = (float)ar;
    g_ctab[idx] = cosf(fa);
    g_stab[idx] = sinf(fa);
}

__global__ void rope_apply_kernel(float* __restrict__ t, int nheads, int total)
{
    int idx = blockIdx.x * blockDim.x + threadIdx.x;
    if (idx >= total) return;
    int p = idx & 63;
    int rest = idx >> 6;
    int tok = rest / nheads;
    int pos = tok & (SEQ - 1);

    float c = g_ctab[pos * 64 + p];
    float s = g_stab[pos * 64 + p];

    float2* base = (float2*)(t + (size_t)rest * HD + 2 * p);
    float2 ab = *base;
    float2 o;
    o.x = ab.x * c - ab.y * s;
    o.y = ab.x * s + ab.y * c;
    *base = o;
}

// ---------------- fp16 WMMA flash attention (unchanged from R13) -------------
#define AT_LDH 136
#define AT_LDS 72
#define AT_LDO 132
#define ATTN_H_SMEM (3 * 64 * AT_LDH * 2 + 64 * AT_LDS * 4 + 64 * AT_LDS * 2 \
                     + 64 * AT_LDO * 4 + 3 * 64 * 4)

__global__ __launch_bounds__(256, 1) void attn_h_kernel(
    const float* __restrict__ q, const float* __restrict__ k,
    const float* __restrict__ v, __half* __restrict__ o)
{
    extern __shared__ char smraw[];
    __half* Qs  = (__half*)smraw;
    __half* Ks  = Qs + 64 * AT_LDH;
    __half* Vs  = Ks + 64 * AT_LDH;
    float*  Ss  = (float*)(Vs + 64 * AT_LDH);
    __half* P16 = (__half*)(Ss + 64 * AT_LDS);
    float*  PVs = (float*)(P16 + 64 * AT_LDS);
    float*  rowm = PVs + 64 * AT_LDO;
    float*  rowl = rowm + 64;
    float*  salpha = rowl + 64;

    const int tid = threadIdx.x;
    const int tx = tid & 15;
    const int ty = tid >> 4;
    const int warp = tid >> 5;
    const int wm = warp >> 1;
    const int wn = warp & 1;
    const int qtile = blockIdx.x;
    const int bh = blockIdx.y;
    const int b = bh / NH;
    const int h = bh % NH;
    const int kvh = h / (NH / NKV);
    const float scale = 0.08838834764831845f;

#pragma unroll
    for (int i = 0; i < 8; i++) {
        int fid = tid + i * 256;
        int r = fid >> 5;
        int c4 = (fid & 31) << 2;
        int sq = qtile * 64 + r;
        float4 vq = *(const float4*)&q[(((size_t)(b * SEQ + sq)) * NH + h) * HD + c4];
        __half2 h01 = __floats2half2_rn(vq.x * scale, vq.y * scale);
        __half2 h23 = __floats2half2_rn(vq.z * scale, vq.w * scale);
        uint2 pk = { *(unsigned*)&h01, *(unsigned*)&h23 };
        *(uint2*)&Qs[r * AT_LDH + c4] = pk;
    }
    if (tid < 64) { rowm[tid] = -INFINITY; rowl[tid] = 0.0f; }

    float Oacc[4][8];
#pragma unroll
    for (int i = 0; i < 4; i++)
#pragma unroll
        for (int cc = 0; cc < 8; cc++) Oacc[i][cc] = 0.0f;
    __syncthreads();

    for (int kt = 0; kt <= qtile; kt++) {
#pragma unroll
        for (int i = 0; i < 8; i++) {
            int fid = tid + i * 256;
            int r = fid >> 5;
            int c4 = (fid & 31) << 2;
            int sk = kt * 64 + r;
            size_t gidx = (((size_t)(b * SEQ + sk)) * NKV + kvh) * HD + c4;
            float4 kv4 = *(const float4*)&k[gidx];
            float4 vv4 = *(const float4*)&v[gidx];
            __half2 k01 = __floats2half2_rn(kv4.x, kv4.y);
            __half2 k23 = __floats2half2_rn(kv4.z, kv4.w);
            __half2 v01 = __floats2half2_rn(vv4.x, vv4.y);
            __half2 v23 = __floats2half2_rn(vv4.z, vv4.w);
            uint2 kk2 = { *(unsigned*)&k01, *(unsigned*)&k23 };
            uint2 vv2 = { *(unsigned*)&v01, *(unsigned*)&v23 };
            *(uint2*)&Ks[r * AT_LDH + c4] = kk2;
            *(uint2*)&Vs[r * AT_LDH + c4] = vv2;
        }
        __syncthreads();

        {
            wmma::fragment<wmma::accumulator, 16, 16, 16, float> sfrag[2];
#pragma unroll
            for (int j = 0; j < 2; j++) wmma::fill_fragment(sfrag[j], 0.0f);
#pragma unroll
            for (int kk = 0; kk < 128; kk += 16) {
                wmma::fragment<wmma::matrix_a, 16, 16, 16, __half, wmma::row_major> aq;
                wmma::load_matrix_sync(aq, &Qs[(wm * 16) * AT_LDH + kk], AT_LDH);
#pragma unroll
                for (int j = 0; j < 2; j++) {
                    wmma::fragment<wmma::matrix_b, 16, 16, 16, __half, wmma::col_major> bk;
                    wmma::load_matrix_sync(bk, &Ks[(wn * 32 + j * 16) * AT_LDH + kk], AT_LDH);
                    wmma::mma_sync(sfrag[j], aq, bk, sfrag[j]);
                }
            }
#pragma unroll
            for (int j = 0; j < 2; j++)
                wmma::store_matrix_sync(&Ss[(wm * 16) * AT_LDS + wn * 32 + j * 16],
                                        sfrag[j], AT_LDS, wmma::mem_row_major);
        }
        __syncthreads();

        const bool diag = (kt == qtile);
        if (diag) {
            for (int idx2 = tid; idx2 < 4096; idx2 += 256) {
                int r = idx2 >> 6, c = idx2 & 63;
                if (c > r) Ss[r * AT_LDS + c] = -1e9f;
            }
            __syncthreads();
        }

        if (tid < 64) {
            float mold = rowm[tid];
            float mx = mold;
            const float* sr = &Ss[tid * AT_LDS];
#pragma unroll 8
            for (int c = 0; c < 64; c++) mx = fmaxf(mx, sr[c]);
            rowm[tid] = mx;
            salpha[tid] = __expf(mold - mx);
        }
        __syncthreads();

        for (int idx2 = tid; idx2 < 4096; idx2 += 256) {
            int r = idx2 >> 6, c = idx2 & 63;
            float p = __expf(Ss[r * AT_LDS + c] - rowm[r]);
            Ss[r * AT_LDS + c] = p;
            P16[r * AT_LDS + c] = __float2half_rn(p);
        }
        __syncthreads();

        if (tid < 64) {
            float ssum = 0.0f;
            const float* sr = &Ss[tid * AT_LDS];
#pragma unroll 8
            for (int c = 0; c < 64; c++) ssum += sr[c];
            rowl[tid] = rowl[tid] * salpha[tid] + ssum;
        }

        {
            wmma::fragment<wmma::accumulator, 16, 16, 16, float> ofrag[4];
#pragma unroll
            for (int j = 0; j < 4; j++) wmma::fill_fragment(ofrag[j], 0.0f);
#pragma unroll
            for (int cs = 0; cs < 64; cs += 16) {
                wmma::fragment<wmma::matrix_a, 16, 16, 16, __half, wmma::row_major> ap;
                wmma::load_matrix_sync(ap, &P16[(wm * 16) * AT_LDS + cs], AT_LDS);
#pragma unroll
                for (int j = 0; j < 4; j++) {
                    wmma::fragment<wmma::matrix_b, 16, 16, 16, __half, wmma::row_major> bv;
                    wmma::load_matrix_sync(bv, &Vs[cs * AT_LDH + wn * 64 + j * 16], AT_LDH);
                    wmma::mma_sync(ofrag[j], ap, bv, ofrag[j]);
                }
            }
#pragma unroll
            for (int j = 0; j < 4; j++)
                wmma::store_matrix_sync(&PVs[(wm * 16) * AT_LDO + wn * 64 + j * 16],
                                        ofrag[j], AT_LDO, wmma::mem_row_major);
        }
        __syncthreads();

#pragma unroll
        for (int i = 0; i < 4; i++) {
            int r = ty + 16 * i;
            float a = salpha[r];
            const float* pv = &PVs[r * AT_LDO + tx * 8];
#pragma unroll
            for (int cc = 0; cc < 8; cc++)
                Oacc[i][cc] = Oacc[i][cc] * a + pv[cc];
        }
        __syncthreads();
    }

#pragma unroll
    for (int i = 0; i < 4; i++) {
        int r = ty + 16 * i;
        int sq = qtile * 64 + r;
        float invl = 1.0f / rowl[r];
        __half2 p0 = __floats2half2_rn(Oacc[i][0] * invl, Oacc[i][1] * invl);
        __half2 p1 = __floats2half2_rn(Oacc[i][2] * invl, Oacc[i][3] * invl);
        __half2 p2 = __floats2half2_rn(Oacc[i][4] * invl, Oacc[i][5] * invl);
        __half2 p3 = __floats2half2_rn(Oacc[i][6] * invl, Oacc[i][7] * invl);
        uint4 pk = { *(unsigned*)&p0, *(unsigned*)&p1, *(unsigned*)&p2, *(unsigned*)&p3 };
        *(uint4*)&o[(((size_t)(b * SEQ + sq)) * NH + h) * HD + tx * 8] = pk;
    }
}

// ---------------- launch ------------------------------------------------------
extern "C" void kernel_launch(void* const* d_in, const int* in_sizes, int n_in,
                              void* d_out, int out_size)
{
    const float* x  = (const float*)d_in[0];
    const float* wq = (const float*)d_in[1];
    const float* wk = (const float*)d_in[2];
    const float* wv = (const float*)d_in[3];
    const float* wo = (const float*)d_in[4];
    float* out = (float*)d_out;

    float*  q;  cudaGetSymbolAddress((void**)&q,  g_q);
    float*  k;  cudaGetSymbolAddress((void**)&k,  g_k);
    float*  v;  cudaGetSymbolAddress((void**)&v,  g_v);
    __half* ah; cudaGetSymbolAddress((void**)&ah, g_attn_h);
    __half* xh; cudaGetSymbolAddress((void**)&xh, g_xh);
    __half* wqh; cudaGetSymbolAddress((void**)&wqh, g_wqh);
    __half* wkh; cudaGetSymbolAddress((void**)&wkh, g_wkh);
    __half* wvh; cudaGetSymbolAddress((void**)&wvh, g_wvh);
    __half* woh; cudaGetSymbolAddress((void**)&woh, g_woh);

    cudaFuncSetAttribute(gemm_h, cudaFuncAttributeMaxDynamicSharedMemorySize,
                         GEMM_H_SMEM);
    cudaFuncSetAttribute(gemm_h_qkv, cudaFuncAttributeMaxDynamicSharedMemorySize,
                         GEMM_H_SMEM);
    cudaFuncSetAttribute(attn_h_kernel, cudaFuncAttributeMaxDynamicSharedMemorySize,
                         ATTN_H_SMEM);

    // fp32 -> fp16 conversion, MLP=4 (4 float4s in flight per thread)
    {
        int n4x = MTOK * DIMSZ / 4;
        int n4q = DIMSZ * NH * HD / 4;
        int n4k = DIMSZ * NKV * HD / 4;
        f2h_kernel<<<(n4x / 4 + 255) / 256, 256>>>(x,  xh,  n4x);
        f2h_kernel<<<(n4q / 4 + 255) / 256, 256>>>(wq, wqh, n4q);
        f2h_kernel<<<(n4k / 4 + 255) / 256, 256>>>(wk, wkh, n4k);
        f2h_kernel<<<(n4k / 4 + 255) / 256, 256>>>(wv, wvh, n4k);
        f2h_kernel<<<(n4q / 4 + 255) / 256, 256>>>(wo, woh, n4q);
    }

    // RoPE table
    rope_table_kernel<<<(SEQ * 64 + 255) / 256, 256>>>();

    // Fused QKV projection
    gemm_h_qkv<<<dim3((NH * HD + 2 * NKV * HD) / 128, MTOK / 128), 256,
                 GEMM_H_SMEM>>>(xh, wqh, wkh, wvh, q, k, v);

    // RoPE on q and k
    {
        int totq = MTOK * NH * (HD / 2);
        int totk = MTOK * NKV * (HD / 2);
        rope_apply_kernel<<<(totq + 255) / 256, 256>>>(q, NH, totq);
        rope_apply_kernel<<<(totk + 255) / 256, 256>>>(k, NKV, totk);
    }

    // Flash attention
    attn_h_kernel<<<dim3(SEQ / 64, BATCH * NH), 256, ATTN_H_SMEM>>>(q, k, v, ah);

    // Output projection
    gemm_h<<<dim3(DIMSZ / 128, MTOK / 128), 256, GEMM_H_SMEM>>>(ah, woh, out, DIMSZ, DIMSZ);
}

// round 16
// speedup vs baseline: 5.1548x; 1.0688x over previous
// Round 16: fp16 end-to-end attention datapath — rope writes fp16 (scale folded
// for Q), V pre-converted, cp.async K/V tiles, persistent Q fragments, fused
// mask+max / exp+sum passes. GEMMs unchanged (near legacy-HMMA ceiling).
#include <cuda_runtime.h>
#include <cuda_fp16.h>
#include <mma.h>
#include <math.h>
#include <cstdint>

using namespace nvcuda;

#define BATCH 2
#define SEQ   2048
#define DIMSZ 4096
#define NH    32
#define NKV   8
#define HD    128
#define MTOK  (BATCH * SEQ)   // 4096 tokens

// ---------------- scratch (static device memory; no allocs allowed) ----------
__device__ float  g_q[(size_t)MTOK * NH * HD];
__device__ float  g_k[(size_t)MTOK * NKV * HD];
__device__ float  g_v[(size_t)MTOK * NKV * HD];
__device__ __half g_qh[(size_t)MTOK * NH * HD];     // rope(q)*scale, fp16
__device__ __half g_kh[(size_t)MTOK * NKV * HD];    // rope(k), fp16
__device__ __half g_vh[(size_t)MTOK * NKV * HD];    // v, fp16
__device__ __half g_attn_h[(size_t)MTOK * NH * HD];
__device__ __half g_xh[(size_t)MTOK * DIMSZ];
__device__ __half g_wqh[(size_t)DIMSZ * NH * HD];
__device__ __half g_wkh[(size_t)DIMSZ * NKV * HD];
__device__ __half g_wvh[(size_t)DIMSZ * NKV * HD];
__device__ __half g_woh[(size_t)NH * HD * DIMSZ];
__device__ float  g_ctab[SEQ * 64];
__device__ float  g_stab[SEQ * 64];

// ---------------- fp32 -> fp16 conversion, MLP=4 -----------------------------
__global__ void f2h_kernel(const float* __restrict__ in, __half* __restrict__ out,
                           int n4)
{
    int i = blockIdx.x * blockDim.x + threadIdx.x;
    const int stride = gridDim.x * blockDim.x;
    float4 v0, v1, v2, v3;
    int i1 = i + stride, i2 = i + 2 * stride, i3 = i + 3 * stride;
    bool p0 = i < n4, p1 = i1 < n4, p2 = i2 < n4, p3 = i3 < n4;
    if (p0) v0 = ((const float4*)in)[i];
    if (p1) v1 = ((const float4*)in)[i1];
    if (p2) v2 = ((const float4*)in)[i2];
    if (p3) v3 = ((const float4*)in)[i3];
    uint2 o0, o1, o2, o3;
    {
        __half2 a = __floats2half2_rn(v0.x, v0.y), b = __floats2half2_rn(v0.z, v0.w);
        o0.x = *(unsigned*)&a; o0.y = *(unsigned*)&b;
        a = __floats2half2_rn(v1.x, v1.y); b = __floats2half2_rn(v1.z, v1.w);
        o1.x = *(unsigned*)&a; o1.y = *(unsigned*)&b;
        a = __floats2half2_rn(v2.x, v2.y); b = __floats2half2_rn(v2.z, v2.w);
        o2.x = *(unsigned*)&a; o2.y = *(unsigned*)&b;
        a = __floats2half2_rn(v3.x, v3.y); b = __floats2half2_rn(v3.z, v3.w);
        o3.x = *(unsigned*)&a; o3.y = *(unsigned*)&b;
    }
    if (p0) ((uint2*)out)[i]  = o0;
    if (p1) ((uint2*)out)[i1] = o1;
    if (p2) ((uint2*)out)[i2] = o2;
    if (p3) ((uint2*)out)[i3] = o3;
}

// ---------------- cp.async helpers -------------------------------------------
__device__ __forceinline__ void cp_async16h(__half* dst, const __half* src) {
    unsigned s = (unsigned)__cvta_generic_to_shared(dst);
    asm volatile("cp.async.cg.shared.global [%0], [%1], 16;\n" :: "r"(s), "l"(src));
}

// ---------------- fp16-in GEMM (unchanged from R15) --------------------------
#define GA_LD 40
#define GB_LD 136
#define GSTG  (128 * GA_LD + 32 * GB_LD)
#define GEMM_H_SMEM (4 * GSTG * 2)

__device__ __forceinline__ void gemm_h_core(
    const __half* __restrict__ A, const __half* __restrict__ B,
    float* __restrict__ C, int Ndim, int Kdim, int bm, int bn, __half* hsm)
{
    const int tid  = threadIdx.x;
    const int warp = tid >> 5;
    const int wr = warp >> 1;
    const int wc = warp & 1;

    const int ar = tid >> 2;
    const int ac = (tid & 3) * 8;
    const int br = tid >> 4;
    const int bc = (tid & 15) * 8;

    auto issue = [&](int it) {
        const int k0 = it << 5;
        __half* As = hsm + (it & 3) * GSTG;
        __half* Bs = As + 128 * GA_LD;
        cp_async16h(&As[ar * GA_LD + ac],        &A[(size_t)(bm + ar) * Kdim + k0 + ac]);
        cp_async16h(&As[(ar + 64) * GA_LD + ac], &A[(size_t)(bm + ar + 64) * Kdim + k0 + ac]);
        cp_async16h(&Bs[br * GB_LD + bc],        &B[(size_t)(k0 + br) * Ndim + bn + bc]);
        cp_async16h(&Bs[(br + 16) * GB_LD + bc], &B[(size_t)(k0 + br + 16) * Ndim + bn + bc]);
        asm volatile("cp.async.commit_group;\n" ::: "memory");
    };

    wmma::fragment<wmma::accumulator, 16, 16, 16, float> acc[2][4];
#pragma unroll
    for (int i = 0; i < 2; i++)
#pragma unroll
        for (int j = 0; j < 4; j++)
            wmma::fill_fragment(acc[i][j], 0.0f);

    const int niter = Kdim >> 5;
    issue(0);
    issue(1);
    issue(2);

    for (int it = 0; it < niter; it++) {
        if (it + 2 < niter) {
            asm volatile("cp.async.wait_group 2;\n" ::: "memory");
        } else if (it + 1 < niter) {
            asm volatile("cp.async.wait_group 1;\n" ::: "memory");
        } else {
            asm volatile("cp.async.wait_group 0;\n" ::: "memory");
        }
        __syncthreads();

        if (it + 3 < niter) issue(it + 3);

        const __half* As = hsm + (it & 3) * GSTG;
        const __half* Bs = As + 128 * GA_LD;

#pragma unroll
        for (int kk = 0; kk < 32; kk += 16) {
            wmma::fragment<wmma::matrix_a, 16, 16, 16, __half, wmma::row_major> af[2];
            wmma::fragment<wmma::matrix_b, 16, 16, 16, __half, wmma::row_major> bf[4];
#pragma unroll
            for (int i = 0; i < 2; i++)
                wmma::load_matrix_sync(af[i], &As[(wr * 32 + i * 16) * GA_LD + kk], GA_LD);
#pragma unroll
            for (int j = 0; j < 4; j++)
                wmma::load_matrix_sync(bf[j], &Bs[kk * GB_LD + wc * 64 + j * 16], GB_LD);
#pragma unroll
            for (int i = 0; i < 2; i++)
#pragma unroll
                for (int j = 0; j < 4; j++)
                    wmma::mma_sync(acc[i][j], af[i], bf[j], acc[i][j]);
        }
    }

#pragma unroll
    for (int i = 0; i < 2; i++)
#pragma unroll
        for (int j = 0; j < 4; j++)
            wmma::store_matrix_sync(
                &C[(size_t)(bm + wr * 32 + i * 16) * Ndim + bn + wc * 64 + j * 16],
                acc[i][j], Ndim, wmma::mem_row_major);
}

__global__ __launch_bounds__(256, 2) void gemm_h(
    const __half* __restrict__ A, const __half* __restrict__ B,
    float* __restrict__ C, int Ndim, int Kdim)
{
    extern __shared__ __half hsm[];
    gemm_h_core(A, B, C, Ndim, Kdim, blockIdx.y * 128, blockIdx.x * 128, hsm);
}

__global__ __launch_bounds__(256, 2) void gemm_h_qkv(
    const __half* __restrict__ xh,
    const __half* __restrict__ wqh, const __half* __restrict__ wkh,
    const __half* __restrict__ wvh,
    float* __restrict__ q, float* __restrict__ k, float* __restrict__ v)
{
    extern __shared__ __half hsm[];
    const int bnTot = blockIdx.x * 128;
    const __half* W;
    float* Out;
    int Nw, bn;
    if (bnTot < NH * HD)                 { W = wqh; Out = q; Nw = NH * HD;  bn = bnTot; }
    else if (bnTot < NH * HD + NKV * HD) { W = wkh; Out = k; Nw = NKV * HD; bn = bnTot - NH * HD; }
    else                                 { W = wvh; Out = v; Nw = NKV * HD; bn = bnTot - NH * HD - NKV * HD; }
    gemm_h_core(xh, W, Out, Nw, DIMSZ, blockIdx.y * 128, bn, hsm);
}

// ---------------- RoPE: table + fp16-output apply ----------------------------
__global__ void rope_table_kernel()
{
    int idx = blockIdx.x * blockDim.x + threadIdx.x;
    if (idx >= SEQ * 64) return;
    int pos = idx >> 6;
    int p = idx & 63;
    double inv = exp(((double)(-2 * p) / 128.0) * log(500000.0));
    float angf = (float)pos * (float)inv;
    double ar = fmod((double)angf, 6.283185307179586476925287);
    float fa = (float)ar;
    g_ctab[idx] = cosf(fa);
    g_stab[idx] = sinf(fa);
}

// rope in fp32, then *scl, then round to fp16 — identical roundings to R15's
// (rope fp32 store) + (attn: *scale, cvt) sequence.
__global__ void rope_apply_h_kernel(const float* __restrict__ in,
                                    __half* __restrict__ out,
                                    int nheads, int total, float scl)
{
    int idx = blockIdx.x * blockDim.x + threadIdx.x;
    if (idx >= total) return;
    int p = idx & 63;
    int rest = idx >> 6;
    int tok = rest / nheads;
    int pos = tok & (SEQ - 1);

    float c = g_ctab[pos * 64 + p];
    float s = g_stab[pos * 64 + p];

    float2 ab = *(const float2*)(in + (size_t)rest * HD + 2 * p);
    float ox = (ab.x * c - ab.y * s) * scl;
    float oy = (ab.x * s + ab.y * c) * scl;
    __half2 hh = __floats2half2_rn(ox, oy);
    *(__half2*)(out + (size_t)rest * HD + 2 * p) = hh;
}

// ---------------- fp16 WMMA flash attention (fp16 inputs) --------------------
// grid (32 q-tiles, 64 batch*head), block 256 (8 warps: 4M x 2N).
// Q lives in persistent A-fragments; K/V stream via cp.async; softmax fp32.
#define AT_LDH 136   // K/V row stride (halfs): 272 B, 16B-aligned
#define AT_LDS 72    // S fp32 / P16 stride
#define AT_LDO 132   // PV fp32 stride
#define OFF_KS  0
#define OFF_VS  (64 * AT_LDH * 2)
#define OFF_SS  (2 * 64 * AT_LDH * 2)
#define OFF_P16 (OFF_SS + 64 * AT_LDS * 4)
#define OFF_PVS (OFF_P16 + 64 * AT_LDS * 2)
#define OFF_STAT (OFF_PVS + 64 * AT_LDO * 4)
#define ATTN_H_SMEM (OFF_STAT + 3 * 64 * 4)

__global__ __launch_bounds__(256, 1) void attn_h_kernel(
    const __half* __restrict__ qh, const __half* __restrict__ kh,
    const __half* __restrict__ vh, __half* __restrict__ o)
{
    extern __shared__ char smraw[];
    __half* Ks  = (__half*)(smraw + OFF_KS);
    __half* Vs  = (__half*)(smraw + OFF_VS);
    float*  Ss  = (float*) (smraw + OFF_SS);
    __half* P16 = (__half*)(smraw + OFF_P16);
    float*  PVs = (float*) (smraw + OFF_PVS);
    float*  rowm   = (float*)(smraw + OFF_STAT);
    float*  rowl   = rowm + 64;
    float*  salpha = rowl + 64;

    const int tid = threadIdx.x;
    const int tx = tid & 15;
    const int ty = tid >> 4;
    const int warp = tid >> 5;
    const int wm = warp >> 1;    // 0..3 (M)
    const int wn = warp & 1;     // 0..1 (N)
    const int qtile = blockIdx.x;
    const int bh = blockIdx.y;
    const int b = bh / NH;
    const int h = bh % NH;
    const int kvh = h / (NH / NKV);

    // ---- Stage Q tile (fp16, pre-scaled) through Ks, capture as fragments ----
#pragma unroll
    for (int i = 0; i < 4; i++) {
        int fid = tid + i * 256;         // 1024 chunks of 8 halfs
        int r = fid >> 4;
        int c8 = (fid & 15) * 8;
        int sq = qtile * 64 + r;
        cp_async16h(&Ks[r * AT_LDH + c8],
                    &qh[(((size_t)(b * SEQ + sq)) * NH + h) * HD + c8]);
    }
    asm volatile("cp.async.commit_group;\n" ::: "memory");
    if (tid < 64) { rowm[tid] = -INFINITY; rowl[tid] = 0.0f; }
    asm volatile("cp.async.wait_group 0;\n" ::: "memory");
    __syncthreads();

    wmma::fragment<wmma::matrix_a, 16, 16, 16, __half, wmma::row_major> aq[8];
#pragma unroll
    for (int kk8 = 0; kk8 < 8; kk8++)
        wmma::load_matrix_sync(aq[kk8], &Ks[(wm * 16) * AT_LDH + kk8 * 16], AT_LDH);
    __syncthreads();   // Q fragments captured before K overwrites Ks

    float Oacc[4][8];
#pragma unroll
    for (int i = 0; i < 4; i++)
#pragma unroll
        for (int cc = 0; cc < 8; cc++) Oacc[i][cc] = 0.0f;

    // passA/passB mapping: 4 threads per row (quad), 16 cols each
    const int prow = tid >> 2;
    const int pq   = tid & 3;

    for (int kt = 0; kt <= qtile; kt++) {
        // ---- K/V tiles via cp.async (fp16, no staging, no CVT) ----
#pragma unroll
        for (int i = 0; i < 4; i++) {
            int fid = tid + i * 256;
            int r = fid >> 4;
            int c8 = (fid & 15) * 8;
            size_t gidx = (((size_t)(b * SEQ + kt * 64 + r)) * NKV + kvh) * HD + c8;
            cp_async16h(&Ks[r * AT_LDH + c8], &kh[gidx]);
            cp_async16h(&Vs[r * AT_LDH + c8], &vh[gidx]);
        }
        asm volatile("cp.async.commit_group;\n" ::: "memory");
        asm volatile("cp.async.wait_group 0;\n" ::: "memory");
        __syncthreads();

        // ---- S = Q @ K^T (Q from persistent fragments) ----
        {
            wmma::fragment<wmma::accumulator, 16, 16, 16, float> sfrag[2];
#pragma unroll
            for (int j = 0; j < 2; j++) wmma::fill_fragment(sfrag[j], 0.0f);
#pragma unroll
            for (int kk8 = 0; kk8 < 8; kk8++) {
#pragma unroll
                for (int j = 0; j < 2; j++) {
                    wmma::fragment<wmma::matrix_b, 16, 16, 16, __half, wmma::col_major> bk;
                    wmma::load_matrix_sync(bk, &Ks[(wn * 32 + j * 16) * AT_LDH + kk8 * 16],
                                           AT_LDH);
                    wmma::mma_sync(sfrag[j], aq[kk8], bk, sfrag[j]);
                }
            }
#pragma unroll
            for (int j = 0; j < 2; j++)
                wmma::store_matrix_sync(&Ss[(wm * 16) * AT_LDS + wn * 32 + j * 16],
                                        sfrag[j], AT_LDS, wmma::mem_row_major);
        }
        __syncthreads();

        const bool diag = (kt == qtile);

        // ---- pass A: fused causal-mask + row-max (quad shuffle) ----
        {
            const float* sr = &Ss[prow * AT_LDS + pq * 16];
            float mx = -INFINITY;
#pragma unroll
            for (int j = 0; j < 16; j++) {
                int c = pq * 16 + j;
                float sv = sr[j];
                if (!(diag && c > prow)) mx = fmaxf(mx, sv);
            }
            mx = fmaxf(mx, __shfl_xor_sync(0xFFFFFFFFu, mx, 1));
            mx = fmaxf(mx, __shfl_xor_sync(0xFFFFFFFFu, mx, 2));
            float mold = rowm[prow];          // warp-uniform read before lockstep write
            float mnew = fmaxf(mold, mx);
            if (pq == 0) {
                rowm[prow] = mnew;
                salpha[prow] = __expf(mold - mnew);
            }
        }
        __syncthreads();

        // ---- pass B: fused exp + P16 store + row-sum (quad shuffle) ----
        {
            const float* sr = &Ss[prow * AT_LDS + pq * 16];
            float m = rowm[prow];
            float ssum = 0.0f;
            __half ph[16];
#pragma unroll
            for (int j = 0; j < 16; j++) {
                int c = pq * 16 + j;
                float p = (diag && c > prow) ? 0.0f : __expf(sr[j] - m);
                ssum += p;
                ph[j] = __float2half_rn(p);
            }
            *(uint4*)&P16[prow * AT_LDS + pq * 16]     = *(uint4*)&ph[0];
            *(uint4*)&P16[prow * AT_LDS + pq * 16 + 8] = *(uint4*)&ph[8];
            ssum += __shfl_xor_sync(0xFFFFFFFFu, ssum, 1);
            ssum += __shfl_xor_sync(0xFFFFFFFFu, ssum, 2);
            if (pq == 0) rowl[prow] = rowl[prow] * salpha[prow] + ssum;
        }
        __syncthreads();

        // ---- PV = P16 @ Vs ----
        {
            wmma::fragment<wmma::accumulator, 16, 16, 16, float> ofrag[4];
#pragma unroll
            for (int j = 0; j < 4; j++) wmma::fill_fragment(ofrag[j], 0.0f);
#pragma unroll
            for (int cs = 0; cs < 64; cs += 16) {
                wmma::fragment<wmma::matrix_a, 16, 16, 16, __half, wmma::row_major> ap;
                wmma::load_matrix_sync(ap, &P16[(wm * 16) * AT_LDS + cs], AT_LDS);
#pragma unroll
                for (int j = 0; j < 4; j++) {
                    wmma::fragment<wmma::matrix_b, 16, 16, 16, __half, wmma::row_major> bv;
                    wmma::load_matrix_sync(bv, &Vs[cs * AT_LDH + wn * 64 + j * 16], AT_LDH);
                    wmma::mma_sync(ofrag[j], ap, bv, ofrag[j]);
                }
            }
#pragma unroll
            for (int j = 0; j < 4; j++)
                wmma::store_matrix_sync(&PVs[(wm * 16) * AT_LDO + wn * 64 + j * 16],
                                        ofrag[j], AT_LDO, wmma::mem_row_major);
        }
        __syncthreads();

        // ---- O = O*alpha + PV (no trailing sync: next iter's load sync covers) ----
#pragma unroll
        for (int i = 0; i < 4; i++) {
            int r = ty + 16 * i;
            float a = salpha[r];
            const float* pv = &PVs[r * AT_LDO + tx * 8];
#pragma unroll
            for (int cc = 0; cc < 8; cc++)
                Oacc[i][cc] = Oacc[i][cc] * a + pv[cc];
        }
    }

    // ---- Normalize + write fp16 ----
#pragma unroll
    for (int i = 0; i < 4; i++) {
        int r = ty + 16 * i;
        int sq = qtile * 64 + r;
        float invl = 1.0f / rowl[r];
        __half2 p0 = __floats2half2_rn(Oacc[i][0] * invl, Oacc[i][1] * invl);
        __half2 p1 = __floats2half2_rn(Oacc[i][2] * invl, Oacc[i][3] * invl);
        __half2 p2 = __floats2half2_rn(Oacc[i][4] * invl, Oacc[i][5] * invl);
        __half2 p3 = __floats2half2_rn(Oacc[i][6] * invl, Oacc[i][7] * invl);
        uint4 pk = { *(unsigned*)&p0, *(unsigned*)&p1, *(unsigned*)&p2, *(unsigned*)&p3 };
        *(uint4*)&o[(((size_t)(b * SEQ + sq)) * NH + h) * HD + tx * 8] = pk;
    }
}

// ---------------- launch ------------------------------------------------------
extern "C" void kernel_launch(void* const* d_in, const int* in_sizes, int n_in,
                              void* d_out, int out_size)
{
    const float* x  = (const float*)d_in[0];
    const float* wq = (const float*)d_in[1];
    const float* wk = (const float*)d_in[2];
    const float* wv = (const float*)d_in[3];
    const float* wo = (const float*)d_in[4];
    float* out = (float*)d_out;

    float*  q;   cudaGetSymbolAddress((void**)&q,   g_q);
    float*  k;   cudaGetSymbolAddress((void**)&k,   g_k);
    float*  v;   cudaGetSymbolAddress((void**)&v,   g_v);
    __half* qh2; cudaGetSymbolAddress((void**)&qh2, g_qh);
    __half* kh2; cudaGetSymbolAddress((void**)&kh2, g_kh);
    __half* vh2; cudaGetSymbolAddress((void**)&vh2, g_vh);
    __half* ah;  cudaGetSymbolAddress((void**)&ah,  g_attn_h);
    __half* xh;  cudaGetSymbolAddress((void**)&xh,  g_xh);
    __half* wqh; cudaGetSymbolAddress((void**)&wqh, g_wqh);
    __half* wkh; cudaGetSymbolAddress((void**)&wkh, g_wkh);
    __half* wvh; cudaGetSymbolAddress((void**)&wvh, g_wvh);
    __half* woh; cudaGetSymbolAddress((void**)&woh, g_woh);

    cudaFuncSetAttribute(gemm_h, cudaFuncAttributeMaxDynamicSharedMemorySize,
                         GEMM_H_SMEM);
    cudaFuncSetAttribute(gemm_h_qkv, cudaFuncAttributeMaxDynamicSharedMemorySize,
                         GEMM_H_SMEM);
    cudaFuncSetAttribute(attn_h_kernel, cudaFuncAttributeMaxDynamicSharedMemorySize,
                         ATTN_H_SMEM);

    // fp32 -> fp16 operand conversion
    {
        int n4x = MTOK * DIMSZ / 4;
        int n4q = DIMSZ * NH * HD / 4;
        int n4k = DIMSZ * NKV * HD / 4;
        f2h_kernel<<<(n4x / 4 + 255) / 256, 256>>>(x,  xh,  n4x);
        f2h_kernel<<<(n4q / 4 + 255) / 256, 256>>>(wq, wqh, n4q);
        f2h_kernel<<<(n4k / 4 + 255) / 256, 256>>>(wk, wkh, n4k);
        f2h_kernel<<<(n4k / 4 + 255) / 256, 256>>>(wv, wvh, n4k);
        f2h_kernel<<<(n4q / 4 + 255) / 256, 256>>>(wo, woh, n4q);
    }

    // RoPE table
    rope_table_kernel<<<(SEQ * 64 + 255) / 256, 256>>>();

    // Fused QKV projection (fp16 in, fp32 out)
    gemm_h_qkv<<<dim3((NH * HD + 2 * NKV * HD) / 128, MTOK / 128), 256,
                 GEMM_H_SMEM>>>(xh, wqh, wkh, wvh, q, k, v);

    // RoPE -> fp16 (Q gets 1/sqrt(HD) folded in); V -> fp16
    {
        int totq = MTOK * NH * (HD / 2);
        int totk = MTOK * NKV * (HD / 2);
        int n4v  = MTOK * NKV * HD / 4;
        rope_apply_h_kernel<<<(totq + 255) / 256, 256>>>(q, qh2, NH, totq,
                                                         0.08838834764831845f);
        rope_apply_h_kernel<<<(totk + 255) / 256, 256>>>(k, kh2, NKV, totk, 1.0f);
        f2h_kernel<<<(n4v / 4 + 255) / 256, 256>>>(v, vh2, n4v);
    }

    // Flash attention (fp16 in/out)
    attn_h_kernel<<<dim3(SEQ / 64, BATCH * NH), 256, ATTN_H_SMEM>>>(qh2, kh2, vh2, ah);

    // Output projection (fp16 in, fp32 out)
    gemm_h<<<dim3(DIMSZ / 128, MTOK / 128), 256, GEMM_H_SMEM>>>(ah, woh, out, DIMSZ, DIMSZ);
}